// round 1
// baseline (speedup 1.0000x reference)
#include <cuda_runtime.h>
#include <math.h>

#define T_TOK  4096
#define DMODEL 512
#define DFF    2048
#define NEXP   16
#define TOPK   2
#define NSLOTS (T_TOK*TOPK)

// ---------------- scratch (device globals; no allocation allowed) ----------------
__device__ float d_H[(size_t)NSLOTS * DFF];      // 64 MB: gelu(x@w1^T+b1) per slot
__device__ float d_Y[(size_t)NSLOTS * DMODEL];   // 16 MB: gate*(h@w2^T+b2) per slot
__device__ int   d_tok[NSLOTS];                  // slot -> token
__device__ float d_gate[NSLOTS];                 // slot -> gate
__device__ int   d_slot_tk[NSLOTS];              // (token,k) -> slot
__device__ int   d_counts[NEXP];
__device__ int   d_off[NEXP];
__device__ int   d_cursor[NEXP];
__device__ int   d_topk_idx[NSLOTS];
__device__ float d_topk_gate[NSLOTS];

// ---------------- small kernels ----------------
__global__ void zero_counts_kernel() {
    if (threadIdx.x < NEXP) d_counts[threadIdx.x] = 0;
}

// one warp per token: 16 logits, softmax, top-2
__global__ void router_kernel(const float* __restrict__ x,
                              const float* __restrict__ rw,
                              const float* __restrict__ rb)
{
    int warp = (blockIdx.x * blockDim.x + threadIdx.x) >> 5;
    int lane = threadIdx.x & 31;
    if (warp >= T_TOK) return;

    const float* xr = x + (size_t)warp * DMODEL;
    float xv[16];
#pragma unroll
    for (int i = 0; i < 16; i++) xv[i] = xr[lane + 32 * i];

    float lg[NEXP];
#pragma unroll
    for (int e = 0; e < NEXP; e++) {
        const float* wr = rw + e * DMODEL;
        float p = 0.f;
#pragma unroll
        for (int i = 0; i < 16; i++) p = fmaf(xv[i], wr[lane + 32 * i], p);
#pragma unroll
        for (int o = 16; o; o >>= 1) p += __shfl_xor_sync(0xffffffffu, p, o);
        lg[e] = p + rb[e];
    }

    if (lane == 0) {
        float mx = lg[0];
#pragma unroll
        for (int e = 1; e < NEXP; e++) mx = fmaxf(mx, lg[e]);
        float pe[NEXP]; float s = 0.f;
#pragma unroll
        for (int e = 0; e < NEXP; e++) { pe[e] = expf(lg[e] - mx); s += pe[e]; }

        // top-2 (ties: lowest index first, matching lax.top_k)
        int i1 = 0; float v1 = pe[0];
#pragma unroll
        for (int e = 1; e < NEXP; e++) if (pe[e] > v1) { v1 = pe[e]; i1 = e; }
        int i2 = (i1 == 0) ? 1 : 0; float v2 = pe[i2];
#pragma unroll
        for (int e = 0; e < NEXP; e++)
            if (e != i1 && e != ((i1 == 0) ? 1 : 0) && pe[e] > v2) { v2 = pe[e]; i2 = e; }

        float inv = 1.f / s;
        d_topk_idx[2 * warp]      = i1;
        d_topk_gate[2 * warp]     = v1 * inv;
        d_topk_idx[2 * warp + 1]  = i2;
        d_topk_gate[2 * warp + 1] = v2 * inv;
        atomicAdd(&d_counts[i1], 1);
        atomicAdd(&d_counts[i2], 1);
    }
}

__global__ void prefix_kernel() {
    int s = 0;
#pragma unroll
    for (int e = 0; e < NEXP; e++) { d_off[e] = s; d_cursor[e] = s; s += d_counts[e]; }
}

__global__ void scatter_kernel() {
    int t = blockIdx.x * blockDim.x + threadIdx.x;
    if (t >= T_TOK) return;
#pragma unroll
    for (int k = 0; k < TOPK; k++) {
        int e = d_topk_idx[2 * t + k];
        int slot = atomicAdd(&d_cursor[e], 1);
        d_tok[slot]  = t;
        d_gate[slot] = d_topk_gate[2 * t + k];
        d_slot_tk[2 * t + k] = slot;
    }
}

// ---------------- GEMM1: H = gelu( gather(x) @ w1^T + b1 ), per expert ----------------
__global__ __launch_bounds__(256, 2)
void gemm1_kernel(const float* __restrict__ x,
                  const float* __restrict__ w1,
                  const float* __restrict__ b1)
{
    const int e   = blockIdx.z;
    const int cnt = d_counts[e];
    const int m0  = blockIdx.y * 128;
    if (m0 >= cnt) return;
    const int n0   = blockIdx.x * 128;
    const int base = d_off[e];

    __shared__ float As[8][128];
    __shared__ float Bs[8][128];

    const int tid  = threadIdx.x;
    const int lrow = tid >> 1;        // 0..127
    const int lk   = (tid & 1) * 4;   // 0 or 4
    const int gm   = m0 + lrow;
    const float* Aptr = (gm < cnt) ? (x + (size_t)d_tok[base + gm] * DMODEL + lk) : nullptr;
    const float* Bptr = w1 + ((size_t)e * DFF + n0 + lrow) * DMODEL + lk;

    const int tx = tid & 15;
    const int ty = tid >> 4;
    float acc[8][8];
#pragma unroll
    for (int i = 0; i < 8; i++)
#pragma unroll
        for (int j = 0; j < 8; j++) acc[i][j] = 0.f;

    for (int k0 = 0; k0 < DMODEL; k0 += 8) {
        float4 av = Aptr ? *(const float4*)(Aptr + k0) : make_float4(0.f, 0.f, 0.f, 0.f);
        float4 bv = *(const float4*)(Bptr + k0);
        __syncthreads();
        As[lk + 0][lrow] = av.x; As[lk + 1][lrow] = av.y;
        As[lk + 2][lrow] = av.z; As[lk + 3][lrow] = av.w;
        Bs[lk + 0][lrow] = bv.x; Bs[lk + 1][lrow] = bv.y;
        Bs[lk + 2][lrow] = bv.z; Bs[lk + 3][lrow] = bv.w;
        __syncthreads();
#pragma unroll
        for (int k = 0; k < 8; k++) {
            float af[8], bf[8];
            *(float4*)(af)     = *(const float4*)(&As[k][ty * 8]);
            *(float4*)(af + 4) = *(const float4*)(&As[k][ty * 8 + 4]);
            *(float4*)(bf)     = *(const float4*)(&Bs[k][tx * 8]);
            *(float4*)(bf + 4) = *(const float4*)(&Bs[k][tx * 8 + 4]);
#pragma unroll
            for (int i = 0; i < 8; i++)
#pragma unroll
                for (int j = 0; j < 8; j++)
                    acc[i][j] = fmaf(af[i], bf[j], acc[i][j]);
        }
    }

    float bv8[8];
    *(float4*)(bv8)     = *(const float4*)(b1 + e * DFF + n0 + tx * 8);
    *(float4*)(bv8 + 4) = *(const float4*)(b1 + e * DFF + n0 + tx * 8 + 4);
#pragma unroll
    for (int i = 0; i < 8; i++) {
        int m = m0 + ty * 8 + i;
        if (m < cnt) {
            float* Hr = d_H + (size_t)(base + m) * DFF + n0 + tx * 8;
            float o[8];
#pragma unroll
            for (int j = 0; j < 8; j++) {
                float v = acc[i][j] + bv8[j];
                o[j] = 0.5f * v * (1.0f + erff(v * 0.7071067811865475f));
            }
            *(float4*)(Hr)     = *(float4*)(o);
            *(float4*)(Hr + 4) = *(float4*)(o + 4);
        }
    }
}

// ---------------- GEMM2: Y = gate * ( H @ w2^T + b2 ), per expert ----------------
__global__ __launch_bounds__(256, 2)
void gemm2_kernel(const float* __restrict__ w2,
                  const float* __restrict__ b2)
{
    const int e   = blockIdx.z;
    const int cnt = d_counts[e];
    const int m0  = blockIdx.y * 128;
    if (m0 >= cnt) return;
    const int n0   = blockIdx.x * 128;
    const int base = d_off[e];

    __shared__ float As[8][128];
    __shared__ float Bs[8][128];

    const int tid  = threadIdx.x;
    const int lrow = tid >> 1;
    const int lk   = (tid & 1) * 4;
    const int gm   = m0 + lrow;
    const float* Aptr = (gm < cnt) ? (d_H + (size_t)(base + gm) * DFF + lk) : nullptr;
    const float* Bptr = w2 + ((size_t)e * DMODEL + n0 + lrow) * DFF + lk;

    const int tx = tid & 15;
    const int ty = tid >> 4;
    float acc[8][8];
#pragma unroll
    for (int i = 0; i < 8; i++)
#pragma unroll
        for (int j = 0; j < 8; j++) acc[i][j] = 0.f;

    for (int k0 = 0; k0 < DFF; k0 += 8) {
        float4 av = Aptr ? *(const float4*)(Aptr + k0) : make_float4(0.f, 0.f, 0.f, 0.f);
        float4 bv = *(const float4*)(Bptr + k0);
        __syncthreads();
        As[lk + 0][lrow] = av.x; As[lk + 1][lrow] = av.y;
        As[lk + 2][lrow] = av.z; As[lk + 3][lrow] = av.w;
        Bs[lk + 0][lrow] = bv.x; Bs[lk + 1][lrow] = bv.y;
        Bs[lk + 2][lrow] = bv.z; Bs[lk + 3][lrow] = bv.w;
        __syncthreads();
#pragma unroll
        for (int k = 0; k < 8; k++) {
            float af[8], bf[8];
            *(float4*)(af)     = *(const float4*)(&As[k][ty * 8]);
            *(float4*)(af + 4) = *(const float4*)(&As[k][ty * 8 + 4]);
            *(float4*)(bf)     = *(const float4*)(&Bs[k][tx * 8]);
            *(float4*)(bf + 4) = *(const float4*)(&Bs[k][tx * 8 + 4]);
#pragma unroll
            for (int i = 0; i < 8; i++)
#pragma unroll
                for (int j = 0; j < 8; j++)
                    acc[i][j] = fmaf(af[i], bf[j], acc[i][j]);
        }
    }

    float bv8[8];
    *(float4*)(bv8)     = *(const float4*)(b2 + e * DMODEL + n0 + tx * 8);
    *(float4*)(bv8 + 4) = *(const float4*)(b2 + e * DMODEL + n0 + tx * 8 + 4);
#pragma unroll
    for (int i = 0; i < 8; i++) {
        int m = m0 + ty * 8 + i;
        if (m < cnt) {
            int slot = base + m;
            float g = d_gate[slot];
            float* Yr = d_Y + (size_t)slot * DMODEL + n0 + tx * 8;
            float o[8];
#pragma unroll
            for (int j = 0; j < 8; j++)
                o[j] = g * (acc[i][j] + bv8[j]);
            *(float4*)(Yr)     = *(float4*)(o);
            *(float4*)(Yr + 4) = *(float4*)(o + 4);
        }
    }
}

// ---------------- combine: out[t] = Y[slot0(t)] + Y[slot1(t)] (deterministic) ----------------
__global__ void combine_kernel(float* __restrict__ out) {
    int t  = blockIdx.x;
    int d4 = threadIdx.x;  // 128 threads x float4 = 512
    int s0 = d_slot_tk[2 * t];
    int s1 = d_slot_tk[2 * t + 1];
    float4 a = *(const float4*)(d_Y + (size_t)s0 * DMODEL + d4 * 4);
    float4 b = *(const float4*)(d_Y + (size_t)s1 * DMODEL + d4 * 4);
    float4 o;
    o.x = a.x + b.x; o.y = a.y + b.y; o.z = a.z + b.z; o.w = a.w + b.w;
    *(float4*)(out + (size_t)t * DMODEL + d4 * 4) = o;
}

// ---------------- launch ----------------
extern "C" void kernel_launch(void* const* d_in, const int* in_sizes, int n_in,
                              void* d_out, int out_size)
{
    const float* x  = (const float*)d_in[0];
    const float* rw = (const float*)d_in[1];
    const float* rb = (const float*)d_in[2];
    const float* w1 = (const float*)d_in[3];
    const float* b1 = (const float*)d_in[4];
    const float* w2 = (const float*)d_in[5];
    const float* b2 = (const float*)d_in[6];
    float* out = (float*)d_out;

    zero_counts_kernel<<<1, 32>>>();
    router_kernel<<<T_TOK / 4, 128>>>(x, rw, rb);
    prefix_kernel<<<1, 1>>>();
    scatter_kernel<<<T_TOK / 256, 256>>>();
    gemm1_kernel<<<dim3(DFF / 128, NSLOTS / 128, NEXP), 256>>>(x, w1, b1);
    gemm2_kernel<<<dim3(DMODEL / 128, NSLOTS / 128, NEXP), 256>>>(w2, b2);
    combine_kernel<<<T_TOK, 128>>>(out);
}

// round 3
// speedup vs baseline: 2.1975x; 2.1975x over previous
#include <cuda_runtime.h>
#include <cuda_bf16.h>
#include <math.h>
#include <stdint.h>

#define T_TOK  4096
#define DMODEL 512
#define DFF    2048
#define NEXP   16
#define TOPK   2
#define NSLOTS (T_TOK*TOPK)

#define BM 128
#define BN 128
#define KC 32            // K elements per stage (32 bf16 = 64B rows)

// smem: 2 stages x 4 arrays x (128 rows x 64B) = 64KB
#define ARR_BYTES   8192
#define OFF_AH      0
#define OFF_AL      8192
#define OFF_BH      16384
#define OFF_BL      24576
#define STAGE_BYTES 32768
#define SMEM_BYTES  65536

// ---------------- scratch (device globals; no allocation allowed) ----------------
__device__ __nv_bfloat16 d_xh[(size_t)T_TOK * DMODEL];
__device__ __nv_bfloat16 d_xl[(size_t)T_TOK * DMODEL];
__device__ __nv_bfloat16 d_w1h[(size_t)NEXP * DFF * DMODEL];
__device__ __nv_bfloat16 d_w1l[(size_t)NEXP * DFF * DMODEL];
__device__ __nv_bfloat16 d_w2h[(size_t)NEXP * DMODEL * DFF];
__device__ __nv_bfloat16 d_w2l[(size_t)NEXP * DMODEL * DFF];
__device__ __nv_bfloat16 d_Hh[(size_t)NSLOTS * DFF];
__device__ __nv_bfloat16 d_Hl[(size_t)NSLOTS * DFF];
__device__ float d_Y[(size_t)NSLOTS * DMODEL];
__device__ int   d_tok[NSLOTS];
__device__ float d_gate[NSLOTS];
__device__ int   d_slot_tk[NSLOTS];
__device__ int   d_counts[NEXP];
__device__ int   d_off[NEXP];
__device__ int   d_cursor[NEXP];
__device__ int   d_topk_idx[NSLOTS];
__device__ float d_topk_gate[NSLOTS];

// ---------------- PTX helpers (sm_80-era: valid on compute_103 base) ----------------
__device__ __forceinline__ uint32_t smem_u32(const void* p) {
    uint32_t a;
    asm("{ .reg .u64 t; cvta.to.shared.u64 t, %1; cvt.u32.u64 %0, t; }" : "=r"(a) : "l"(p));
    return a;
}
__device__ __forceinline__ uint32_t lds32(uint32_t a) {
    uint32_t v;
    asm volatile("ld.shared.b32 %0, [%1];" : "=r"(v) : "r"(a));
    return v;
}
__device__ __forceinline__ void cpa16(uint32_t dst, const void* src, uint32_t srcsz) {
    asm volatile("cp.async.cg.shared.global [%0], [%1], 16, %2;"
                 :: "r"(dst), "l"(src), "r"(srcsz) : "memory");
}
#define CP_COMMIT() asm volatile("cp.async.commit_group;" ::: "memory")
#define CP_WAIT1()  asm volatile("cp.async.wait_group 1;" ::: "memory")

__device__ __forceinline__ void mma16816(float* d, const uint32_t* a, const uint32_t* b) {
    asm volatile("mma.sync.aligned.m16n8k16.row.col.f32.bf16.bf16.f32 "
        "{%0,%1,%2,%3}, {%4,%5,%6,%7}, {%8,%9}, {%0,%1,%2,%3};"
        : "+f"(d[0]), "+f"(d[1]), "+f"(d[2]), "+f"(d[3])
        : "r"(a[0]), "r"(a[1]), "r"(a[2]), "r"(a[3]), "r"(b[0]), "r"(b[1]));
}

// SW64-style swizzle for 64B-pitch rows: conflict-free for the fragment LDS pattern
__device__ __forceinline__ uint32_t swzo(int row, int cb) {
    return (uint32_t)(row * 64 + (cb ^ (((row >> 1) & 3) << 4)));
}

// ---------------- small kernels ----------------
__global__ void zero_counts_kernel() {
    if (threadIdx.x < NEXP) d_counts[threadIdx.x] = 0;
}

__global__ void router_kernel(const float* __restrict__ x,
                              const float* __restrict__ rw,
                              const float* __restrict__ rb)
{
    int warp = (blockIdx.x * blockDim.x + threadIdx.x) >> 5;
    int lane = threadIdx.x & 31;
    if (warp >= T_TOK) return;

    const float* xr = x + (size_t)warp * DMODEL;
    float xv[16];
#pragma unroll
    for (int i = 0; i < 16; i++) xv[i] = xr[lane + 32 * i];

    float lg[NEXP];
#pragma unroll
    for (int e = 0; e < NEXP; e++) {
        const float* wr = rw + e * DMODEL;
        float p = 0.f;
#pragma unroll
        for (int i = 0; i < 16; i++) p = fmaf(xv[i], wr[lane + 32 * i], p);
#pragma unroll
        for (int o = 16; o; o >>= 1) p += __shfl_xor_sync(0xffffffffu, p, o);
        lg[e] = p + rb[e];
    }

    if (lane == 0) {
        float mx = lg[0];
#pragma unroll
        for (int e = 1; e < NEXP; e++) mx = fmaxf(mx, lg[e]);
        float pe[NEXP]; float s = 0.f;
#pragma unroll
        for (int e = 0; e < NEXP; e++) { pe[e] = expf(lg[e] - mx); s += pe[e]; }

        int i1 = 0; float v1 = pe[0];
#pragma unroll
        for (int e = 1; e < NEXP; e++) if (pe[e] > v1) { v1 = pe[e]; i1 = e; }
        int i2 = (i1 == 0) ? 1 : 0; float v2 = pe[i2];
#pragma unroll
        for (int e = 0; e < NEXP; e++)
            if (e != i1 && e != ((i1 == 0) ? 1 : 0) && pe[e] > v2) { v2 = pe[e]; i2 = e; }

        float inv = 1.f / s;
        d_topk_idx[2 * warp]      = i1;
        d_topk_gate[2 * warp]     = v1 * inv;
        d_topk_idx[2 * warp + 1]  = i2;
        d_topk_gate[2 * warp + 1] = v2 * inv;
        atomicAdd(&d_counts[i1], 1);
        atomicAdd(&d_counts[i2], 1);
    }
}

__global__ void prefix_kernel() {
    int s = 0;
#pragma unroll
    for (int e = 0; e < NEXP; e++) { d_off[e] = s; d_cursor[e] = s; s += d_counts[e]; }
}

__global__ void scatter_kernel() {
    int t = blockIdx.x * blockDim.x + threadIdx.x;
    if (t >= T_TOK) return;
#pragma unroll
    for (int k = 0; k < TOPK; k++) {
        int e = d_topk_idx[2 * t + k];
        int slot = atomicAdd(&d_cursor[e], 1);
        d_tok[slot]  = t;
        d_gate[slot] = d_topk_gate[2 * t + k];
        d_slot_tk[2 * t + k] = slot;
    }
}

// fp32 -> (bf16 hi, bf16 lo) split
__global__ void split_kernel(const float* __restrict__ src,
                             __nv_bfloat16* __restrict__ hi,
                             __nv_bfloat16* __restrict__ lo, int n4)
{
    int i = blockIdx.x * blockDim.x + threadIdx.x;
    if (i >= n4) return;
    float4 v = ((const float4*)src)[i];
    __nv_bfloat16 h0 = __float2bfloat16(v.x);
    __nv_bfloat16 h1 = __float2bfloat16(v.y);
    __nv_bfloat16 h2 = __float2bfloat16(v.z);
    __nv_bfloat16 h3 = __float2bfloat16(v.w);
    __nv_bfloat162* H = (__nv_bfloat162*)hi;
    H[2 * i]     = __halves2bfloat162(h0, h1);
    H[2 * i + 1] = __halves2bfloat162(h2, h3);
    __nv_bfloat162* L = (__nv_bfloat162*)lo;
    L[2 * i]     = __halves2bfloat162(__float2bfloat16(v.x - __bfloat162float(h0)),
                                      __float2bfloat16(v.y - __bfloat162float(h1)));
    L[2 * i + 1] = __halves2bfloat162(__float2bfloat16(v.z - __bfloat162float(h2)),
                                      __float2bfloat16(v.w - __bfloat162float(h3)));
}

// ---------------- split-bf16 HMMA grouped GEMM ----------------
// PHASE1: D = gather(x) @ w1^T ; epilogue bias+GELU -> d_Hh/d_Hl
// PHASE2: D = H @ w2^T ;         epilogue gate*(D+bias) -> d_Y
template<int KTOT, bool PHASE1>
__global__ __launch_bounds__(256)
void gemm_mma(const float* __restrict__ bias)
{
    constexpr int NT = PHASE1 ? DFF : DMODEL;
    constexpr int NK = KTOT / KC;
    const int e   = blockIdx.z;
    const int cnt = d_counts[e];
    const int m0  = blockIdx.y * BM;
    if (m0 >= cnt) return;
    const int n0   = blockIdx.x * BN;
    const int base = d_off[e];

    extern __shared__ __align__(128) char smem[];
    const uint32_t su = smem_u32(smem);

    const int tid = threadIdx.x;
    const int wid = tid >> 5;
    const int lid = tid & 31;

    // ---- staging: thread -> (row, two 16B chunks) ----
    const int r  = tid >> 1;
    const int c0 = (tid & 1) * 2;   // 16B chunk index (0..3)
    const int gm = m0 + r;
    const __nv_bfloat16 *arh = d_xh, *arl = d_xl;  // dummies when row OOB
    uint32_t aszA = 0;
    if (gm < cnt) {
        int row = PHASE1 ? d_tok[base + gm] : (base + gm);
        arh = (PHASE1 ? d_xh : d_Hh) + (size_t)row * KTOT;
        arl = (PHASE1 ? d_xl : d_Hl) + (size_t)row * KTOT;
        aszA = 16;
    }
    const __nv_bfloat16* brh = (PHASE1 ? d_w1h : d_w2h) + ((size_t)e * NT + n0 + r) * KTOT;
    const __nv_bfloat16* brl = (PHASE1 ? d_w1l : d_w2l) + ((size_t)e * NT + n0 + r) * KTOT;

    const uint32_t dst0 = swzo(r, c0 * 16);
    const uint32_t dst1 = swzo(r, (c0 + 1) * 16);
    const int ce0 = c0 * 8;           // element offset of chunk 0

    // ---- compute layout ----
    const int wm  = (wid & 1) * 64;   // warp m-offset in tile
    const int wn  = (wid >> 1) * 32;  // warp n-offset in tile
    const int lr  = lid >> 2;         // 0..7
    const int lc4 = (lid & 3) * 4;    // byte offset of k-pair

    float acc[4][4][4];
#pragma unroll
    for (int i = 0; i < 4; i++)
#pragma unroll
        for (int j = 0; j < 4; j++)
#pragma unroll
            for (int q = 0; q < 4; q++) acc[i][j][q] = 0.f;

    auto issue = [&](int it, int buf) {
        const uint32_t sb = su + (uint32_t)buf * STAGE_BYTES;
        const int kb = it * KC;
        cpa16(sb + OFF_AH + dst0, arh + kb + ce0,     aszA);
        cpa16(sb + OFF_AH + dst1, arh + kb + ce0 + 8, aszA);
        cpa16(sb + OFF_AL + dst0, arl + kb + ce0,     aszA);
        cpa16(sb + OFF_AL + dst1, arl + kb + ce0 + 8, aszA);
        cpa16(sb + OFF_BH + dst0, brh + kb + ce0,     16);
        cpa16(sb + OFF_BH + dst1, brh + kb + ce0 + 8, 16);
        cpa16(sb + OFF_BL + dst0, brl + kb + ce0,     16);
        cpa16(sb + OFF_BL + dst1, brl + kb + ce0 + 8, 16);
    };

    issue(0, 0);
    CP_COMMIT();

    for (int it = 0; it < NK; ++it) {
        if (it + 1 < NK) issue(it + 1, (it + 1) & 1);
        CP_COMMIT();
        CP_WAIT1();
        __syncthreads();
        const uint32_t sb = su + (uint32_t)(it & 1) * STAGE_BYTES;

#pragma unroll
        for (int kk = 0; kk < 2; ++kk) {
            const int kb2 = kk * 32;  // byte offset of this k16
            uint32_t Ah[4][4], Al[4][4], Bh[4][2], Bl[4][2];

#pragma unroll
            for (int mf = 0; mf < 4; ++mf) {
                const int r0 = wm + mf * 16 + lr;
                Ah[mf][0] = lds32(sb + OFF_AH + swzo(r0,     kb2 + lc4));
                Ah[mf][1] = lds32(sb + OFF_AH + swzo(r0 + 8, kb2 + lc4));
                Ah[mf][2] = lds32(sb + OFF_AH + swzo(r0,     kb2 + lc4 + 16));
                Ah[mf][3] = lds32(sb + OFF_AH + swzo(r0 + 8, kb2 + lc4 + 16));
            }
#pragma unroll
            for (int nf = 0; nf < 4; ++nf) {
                const int rn = wn + nf * 8 + lr;
                Bh[nf][0] = lds32(sb + OFF_BH + swzo(rn, kb2 + lc4));
                Bh[nf][1] = lds32(sb + OFF_BH + swzo(rn, kb2 + lc4 + 16));
            }
#pragma unroll
            for (int mf = 0; mf < 4; ++mf)
#pragma unroll
                for (int nf = 0; nf < 4; ++nf)
                    mma16816(acc[mf][nf], Ah[mf], Bh[nf]);

#pragma unroll
            for (int nf = 0; nf < 4; ++nf) {
                const int rn = wn + nf * 8 + lr;
                Bl[nf][0] = lds32(sb + OFF_BL + swzo(rn, kb2 + lc4));
                Bl[nf][1] = lds32(sb + OFF_BL + swzo(rn, kb2 + lc4 + 16));
            }
#pragma unroll
            for (int mf = 0; mf < 4; ++mf)
#pragma unroll
                for (int nf = 0; nf < 4; ++nf)
                    mma16816(acc[mf][nf], Ah[mf], Bl[nf]);

#pragma unroll
            for (int mf = 0; mf < 4; ++mf) {
                const int r0 = wm + mf * 16 + lr;
                Al[mf][0] = lds32(sb + OFF_AL + swzo(r0,     kb2 + lc4));
                Al[mf][1] = lds32(sb + OFF_AL + swzo(r0 + 8, kb2 + lc4));
                Al[mf][2] = lds32(sb + OFF_AL + swzo(r0,     kb2 + lc4 + 16));
                Al[mf][3] = lds32(sb + OFF_AL + swzo(r0 + 8, kb2 + lc4 + 16));
            }
#pragma unroll
            for (int mf = 0; mf < 4; ++mf)
#pragma unroll
                for (int nf = 0; nf < 4; ++nf)
                    mma16816(acc[mf][nf], Al[mf], Bh[nf]);
        }
        __syncthreads();
    }

    // ---- epilogue ----
#pragma unroll
    for (int mf = 0; mf < 4; ++mf) {
        const int mrow = m0 + wm + mf * 16 + lr;
#pragma unroll
        for (int half = 0; half < 2; ++half) {
            const int m = mrow + half * 8;
            if (m < cnt) {
                if (PHASE1) {
                    const size_t hb = (size_t)(base + m) * DFF;
#pragma unroll
                    for (int nf = 0; nf < 4; ++nf) {
                        const int c = n0 + wn + nf * 8 + (lid & 3) * 2;
                        const float2 bv = *(const float2*)(bias + (size_t)e * NT + c);
                        float v0 = acc[mf][nf][half * 2 + 0] + bv.x;
                        float v1 = acc[mf][nf][half * 2 + 1] + bv.y;
                        v0 = 0.5f * v0 * (1.0f + erff(v0 * 0.7071067811865475f));
                        v1 = 0.5f * v1 * (1.0f + erff(v1 * 0.7071067811865475f));
                        __nv_bfloat16 h0 = __float2bfloat16(v0);
                        __nv_bfloat16 h1 = __float2bfloat16(v1);
                        *(__nv_bfloat162*)(d_Hh + hb + c) = __halves2bfloat162(h0, h1);
                        *(__nv_bfloat162*)(d_Hl + hb + c) =
                            __halves2bfloat162(__float2bfloat16(v0 - __bfloat162float(h0)),
                                               __float2bfloat16(v1 - __bfloat162float(h1)));
                    }
                } else {
                    const float g = d_gate[base + m];
                    const size_t yb = (size_t)(base + m) * DMODEL;
#pragma unroll
                    for (int nf = 0; nf < 4; ++nf) {
                        const int c = n0 + wn + nf * 8 + (lid & 3) * 2;
                        const float2 bv = *(const float2*)(bias + (size_t)e * NT + c);
                        float2 o;
                        o.x = g * (acc[mf][nf][half * 2 + 0] + bv.x);
                        o.y = g * (acc[mf][nf][half * 2 + 1] + bv.y);
                        *(float2*)(d_Y + yb + c) = o;
                    }
                }
            }
        }
    }
}

// ---------------- combine: out[t] = Y[slot0] + Y[slot1] ----------------
__global__ void combine_kernel(float* __restrict__ out) {
    int t  = blockIdx.x;
    int d4 = threadIdx.x;
    int s0 = d_slot_tk[2 * t];
    int s1 = d_slot_tk[2 * t + 1];
    float4 a = *(const float4*)(d_Y + (size_t)s0 * DMODEL + d4 * 4);
    float4 b = *(const float4*)(d_Y + (size_t)s1 * DMODEL + d4 * 4);
    float4 o;
    o.x = a.x + b.x; o.y = a.y + b.y; o.z = a.z + b.z; o.w = a.w + b.w;
    *(float4*)(out + (size_t)t * DMODEL + d4 * 4) = o;
}

// ---------------- launch ----------------
extern "C" void kernel_launch(void* const* d_in, const int* in_sizes, int n_in,
                              void* d_out, int out_size)
{
    const float* x  = (const float*)d_in[0];
    const float* rw = (const float*)d_in[1];
    const float* rb = (const float*)d_in[2];
    const float* w1 = (const float*)d_in[3];
    const float* b1 = (const float*)d_in[4];
    const float* w2 = (const float*)d_in[5];
    const float* b2 = (const float*)d_in[6];
    float* out = (float*)d_out;

    cudaFuncSetAttribute(gemm_mma<DMODEL, true>,  cudaFuncAttributeMaxDynamicSharedMemorySize, SMEM_BYTES);
    cudaFuncSetAttribute(gemm_mma<DFF,    false>, cudaFuncAttributeMaxDynamicSharedMemorySize, SMEM_BYTES);

    __nv_bfloat16 *xh, *xl, *w1h, *w1l, *w2h, *w2l;
    cudaGetSymbolAddress((void**)&xh,  d_xh);
    cudaGetSymbolAddress((void**)&xl,  d_xl);
    cudaGetSymbolAddress((void**)&w1h, d_w1h);
    cudaGetSymbolAddress((void**)&w1l, d_w1l);
    cudaGetSymbolAddress((void**)&w2h, d_w2h);
    cudaGetSymbolAddress((void**)&w2l, d_w2l);

    zero_counts_kernel<<<1, 32>>>();
    router_kernel<<<T_TOK / 4, 128>>>(x, rw, rb);

    const int nx  = T_TOK * DMODEL / 4;
    const int nw1 = NEXP * DFF * DMODEL / 4;
    const int nw2 = NEXP * DMODEL * DFF / 4;
    split_kernel<<<(nx  + 255) / 256, 256>>>(x,  xh,  xl,  nx);
    split_kernel<<<(nw1 + 255) / 256, 256>>>(w1, w1h, w1l, nw1);
    split_kernel<<<(nw2 + 255) / 256, 256>>>(w2, w2h, w2l, nw2);

    prefix_kernel<<<1, 1>>>();
    scatter_kernel<<<T_TOK / 256, 256>>>();

    gemm_mma<DMODEL, true><<<dim3(DFF / BN, NSLOTS / BM, NEXP), 256, SMEM_BYTES>>>(b1);
    gemm_mma<DFF, false><<<dim3(DMODEL / BN, NSLOTS / BM, NEXP), 256, SMEM_BYTES>>>(b2);

    combine_kernel<<<T_TOK, 128>>>(out);
}

// round 5
// speedup vs baseline: 2.5463x; 1.1587x over previous
#include <cuda_runtime.h>
#include <cuda_fp16.h>
#include <math.h>
#include <stdint.h>

#define T_TOK  4096
#define DMODEL 512
#define DFF    2048
#define NEXP   16
#define TOPK   2
#define NSLOTS (T_TOK*TOPK)

#define BM 128
#define BN 128
#define KC 64            // K elems per stage (64 fp16 = 128B rows)

// smem: 2 stages x (A 16KB + B 16KB) = 64KB
#define OFF_A       0
#define OFF_B       16384
#define STAGE_BYTES 32768
#define SMEM_BYTES  65536

// ---------------- scratch ----------------
__device__ __half d_xf[(size_t)T_TOK * DMODEL];
__device__ __half d_Hf[(size_t)NSLOTS * DFF];
__device__ float d_Y[(size_t)NSLOTS * DMODEL];
__device__ int   d_tok[NSLOTS];
__device__ float d_gate[NSLOTS];
__device__ int   d_slot_tk[NSLOTS];
__device__ int   d_counts[NEXP];
__device__ int   d_off[NEXP];
__device__ int   d_cursor[NEXP];
__device__ int   d_topk_idx[NSLOTS];
__device__ float d_topk_gate[NSLOTS];

// ---------------- PTX helpers ----------------
__device__ __forceinline__ uint32_t smem_u32(const void* p) {
    uint32_t a;
    asm("{ .reg .u64 t; cvta.to.shared.u64 t, %1; cvt.u32.u64 %0, t; }" : "=r"(a) : "l"(p));
    return a;
}
__device__ __forceinline__ uint32_t lds32(uint32_t a) {
    uint32_t v;
    asm volatile("ld.shared.b32 %0, [%1];" : "=r"(v) : "r"(a));
    return v;
}
__device__ __forceinline__ void cpa16(uint32_t dst, const void* src, uint32_t srcsz) {
    asm volatile("cp.async.cg.shared.global [%0], [%1], 16, %2;"
                 :: "r"(dst), "l"(src), "r"(srcsz) : "memory");
}
#define CP_COMMIT() asm volatile("cp.async.commit_group;" ::: "memory")
#define CP_WAIT0()  asm volatile("cp.async.wait_group 0;" ::: "memory")

__device__ __forceinline__ void mma16816(float* d, const uint32_t* a, const uint32_t* b) {
    asm volatile("mma.sync.aligned.m16n8k16.row.col.f32.f16.f16.f32 "
        "{%0,%1,%2,%3}, {%4,%5,%6,%7}, {%8,%9}, {%0,%1,%2,%3};"
        : "+f"(d[0]), "+f"(d[1]), "+f"(d[2]), "+f"(d[3])
        : "r"(a[0]), "r"(a[1]), "r"(a[2]), "r"(a[3]), "r"(b[0]), "r"(b[1]));
}

// pack two floats -> fp16x2 in a u32
__device__ __forceinline__ uint32_t pack_h2(float a, float b) {
    uint32_t r;
    asm("{ .reg .f16 lo, hi; cvt.rn.f16.f32 lo, %1; cvt.rn.f16.f32 hi, %2; mov.b32 %0, {lo, hi}; }"
        : "=r"(r) : "f"(a), "f"(b));
    return r;
}

// SW128 swizzle for 128B-pitch rows
__device__ __forceinline__ uint32_t swz(int row, int cb) {
    return (uint32_t)(row * 128 + (cb ^ ((row & 7) << 4)));
}

// ---------------- small kernels ----------------
__global__ void zero_counts_kernel() {
    if (threadIdx.x < NEXP) d_counts[threadIdx.x] = 0;
}

__global__ void router_kernel(const float* __restrict__ x,
                              const float* __restrict__ rw,
                              const float* __restrict__ rb)
{
    int warp = (blockIdx.x * blockDim.x + threadIdx.x) >> 5;
    int lane = threadIdx.x & 31;
    if (warp >= T_TOK) return;

    const float* xr = x + (size_t)warp * DMODEL;
    float xv[16];
#pragma unroll
    for (int i = 0; i < 16; i++) xv[i] = xr[lane + 32 * i];

    float lg[NEXP];
#pragma unroll
    for (int e = 0; e < NEXP; e++) {
        const float* wr = rw + e * DMODEL;
        float p = 0.f;
#pragma unroll
        for (int i = 0; i < 16; i++) p = fmaf(xv[i], wr[lane + 32 * i], p);
#pragma unroll
        for (int o = 16; o; o >>= 1) p += __shfl_xor_sync(0xffffffffu, p, o);
        lg[e] = p + rb[e];
    }

    if (lane == 0) {
        float mx = lg[0];
#pragma unroll
        for (int e = 1; e < NEXP; e++) mx = fmaxf(mx, lg[e]);
        float pe[NEXP]; float s = 0.f;
#pragma unroll
        for (int e = 0; e < NEXP; e++) { pe[e] = expf(lg[e] - mx); s += pe[e]; }

        int i1 = 0; float v1 = pe[0];
#pragma unroll
        for (int e = 1; e < NEXP; e++) if (pe[e] > v1) { v1 = pe[e]; i1 = e; }
        int i2 = (i1 == 0) ? 1 : 0; float v2 = pe[i2];
#pragma unroll
        for (int e = 0; e < NEXP; e++)
            if (e != i1 && e != ((i1 == 0) ? 1 : 0) && pe[e] > v2) { v2 = pe[e]; i2 = e; }

        float inv = 1.f / s;
        d_topk_idx[2 * warp]      = i1;
        d_topk_gate[2 * warp]     = v1 * inv;
        d_topk_idx[2 * warp + 1]  = i2;
        d_topk_gate[2 * warp + 1] = v2 * inv;
        atomicAdd(&d_counts[i1], 1);
        atomicAdd(&d_counts[i2], 1);
    }
}

__global__ void prefix_kernel() {
    int s = 0;
#pragma unroll
    for (int e = 0; e < NEXP; e++) { d_off[e] = s; d_cursor[e] = s; s += d_counts[e]; }
}

__global__ void scatter_kernel() {
    int t = blockIdx.x * blockDim.x + threadIdx.x;
    if (t >= T_TOK) return;
#pragma unroll
    for (int k = 0; k < TOPK; k++) {
        int e = d_topk_idx[2 * t + k];
        int slot = atomicAdd(&d_cursor[e], 1);
        d_tok[slot]  = t;
        d_gate[slot] = d_topk_gate[2 * t + k];
        d_slot_tk[2 * t + k] = slot;
    }
}

// x fp32 -> fp16
__global__ void xcvt_kernel(const float* __restrict__ x, __half* __restrict__ xf, int n4) {
    int i = blockIdx.x * blockDim.x + threadIdx.x;
    if (i >= n4) return;
    float4 v = ((const float4*)x)[i];
    uint32_t* o = (uint32_t*)xf;
    o[2 * i]     = pack_h2(v.x, v.y);
    o[2 * i + 1] = pack_h2(v.z, v.w);
}

// ---------------- fp16 HMMA grouped GEMM (fused fp32->fp16 B conversion) ----------------
// PHASE1: D = gather(xf) @ w1^T ; epilogue bias+GELU -> d_Hf (fp16)
// PHASE2: D = Hf @ w2^T ;         epilogue gate*(D+bias) -> d_Y (fp32)
template<int KTOT, bool PHASE1>
__global__ __launch_bounds__(256)
void gemm_mma(const float* __restrict__ Bsrc, const float* __restrict__ bias)
{
    constexpr int NT = PHASE1 ? DFF : DMODEL;
    constexpr int NK = KTOT / KC;
    const int e   = blockIdx.z;
    const int cnt = d_counts[e];
    const int m0  = blockIdx.y * BM;
    if (m0 >= cnt) return;
    const int n0   = blockIdx.x * BN;
    const int base = d_off[e];

    extern __shared__ __align__(128) char smem[];
    const uint32_t su = smem_u32(smem);

    const int tid = threadIdx.x;
    const int wid = tid >> 5;
    const int lid = tid & 31;

    // ---- staging roles: thread -> row r, 32-elem half ----
    const int r    = tid >> 1;
    const int half = tid & 1;
    const int gm   = m0 + r;
    const __half* arow = d_xf;
    uint32_t aszA = 0;
    if (gm < cnt) {
        int row = PHASE1 ? d_tok[base + gm] : (base + gm);
        arow = (PHASE1 ? d_xf : d_Hf) + (size_t)row * KTOT;
        aszA = 16;
    }
    const float* brow = Bsrc + ((size_t)e * NT + n0 + r) * KTOT;

    uint32_t dstc[4];
#pragma unroll
    for (int j = 0; j < 4; j++) dstc[j] = swz(r, half * 64 + j * 16);

    // ---- compute layout ----
    const int wm  = (wid & 1) * 64;
    const int wn  = (wid >> 1) * 32;
    const int lr  = lid >> 2;
    const int lc4 = (lid & 3) * 4;

    float acc[4][4][4];
#pragma unroll
    for (int i = 0; i < 4; i++)
#pragma unroll
        for (int j = 0; j < 4; j++)
#pragma unroll
            for (int q = 0; q < 4; q++) acc[i][j][q] = 0.f;

    float4 bq[8];

    auto ldgB = [&](int it) {
        const float* p = brow + it * KC + half * 32;
#pragma unroll
        for (int j = 0; j < 8; j++) bq[j] = *(const float4*)(p + j * 4);
    };
    auto issueA = [&](int it, int buf) {
        const uint32_t sb = su + (uint32_t)buf * STAGE_BYTES + OFF_A;
        const __half* p = arow + it * KC + half * 32;
#pragma unroll
        for (int j = 0; j < 4; j++) cpa16(sb + dstc[j], p + j * 8, aszA);
    };
    auto stsB = [&](int buf) {
        char* sb = smem + buf * STAGE_BYTES + OFF_B;
#pragma unroll
        for (int j = 0; j < 4; j++) {
            const float4 q0 = bq[2 * j], q1 = bq[2 * j + 1];
            uint4 u;
            u.x = pack_h2(q0.x, q0.y);
            u.y = pack_h2(q0.z, q0.w);
            u.z = pack_h2(q1.x, q1.y);
            u.w = pack_h2(q1.z, q1.w);
            *(uint4*)(sb + dstc[j]) = u;
        }
    };

    // prologue: stage 0
    ldgB(0);
    issueA(0, 0);
    CP_COMMIT();
    stsB(0);
    CP_WAIT0();
    __syncthreads();

    for (int it = 0; it < NK; ++it) {
        const int buf = it & 1;
        if (it + 1 < NK) {
            ldgB(it + 1);
            issueA(it + 1, buf ^ 1);
            CP_COMMIT();
        }

        const uint32_t sa  = su + (uint32_t)buf * STAGE_BYTES + OFF_A;
        const uint32_t sbb = su + (uint32_t)buf * STAGE_BYTES + OFF_B;
#pragma unroll
        for (int kk = 0; kk < 4; ++kk) {
            const int kb2 = kk * 32;
            uint32_t Af[4][4], Bf[4][2];
#pragma unroll
            for (int mf = 0; mf < 4; ++mf) {
                const int r0 = wm + mf * 16 + lr;
                Af[mf][0] = lds32(sa + swz(r0,     kb2 + lc4));
                Af[mf][1] = lds32(sa + swz(r0 + 8, kb2 + lc4));
                Af[mf][2] = lds32(sa + swz(r0,     kb2 + lc4 + 16));
                Af[mf][3] = lds32(sa + swz(r0 + 8, kb2 + lc4 + 16));
            }
#pragma unroll
            for (int nf = 0; nf < 4; ++nf) {
                const int rn = wn + nf * 8 + lr;
                Bf[nf][0] = lds32(sbb + swz(rn, kb2 + lc4));
                Bf[nf][1] = lds32(sbb + swz(rn, kb2 + lc4 + 16));
            }
#pragma unroll
            for (int mf = 0; mf < 4; ++mf)
#pragma unroll
                for (int nf = 0; nf < 4; ++nf)
                    mma16816(acc[mf][nf], Af[mf], Bf[nf]);
        }

        if (it + 1 < NK) {
            stsB(buf ^ 1);
            CP_WAIT0();
        }
        __syncthreads();
    }

    // ---- epilogue ----
#pragma unroll
    for (int mf = 0; mf < 4; ++mf) {
        const int mrow = m0 + wm + mf * 16 + lr;
#pragma unroll
        for (int hh = 0; hh < 2; ++hh) {
            const int m = mrow + hh * 8;
            if (m < cnt) {
                if (PHASE1) {
                    const size_t hb = (size_t)(base + m) * DFF;
#pragma unroll
                    for (int nf = 0; nf < 4; ++nf) {
                        const int c = n0 + wn + nf * 8 + (lid & 3) * 2;
                        const float2 bv = *(const float2*)(bias + (size_t)e * NT + c);
                        float v0 = acc[mf][nf][hh * 2 + 0] + bv.x;
                        float v1 = acc[mf][nf][hh * 2 + 1] + bv.y;
                        v0 = 0.5f * v0 * (1.0f + erff(v0 * 0.7071067811865475f));
                        v1 = 0.5f * v1 * (1.0f + erff(v1 * 0.7071067811865475f));
                        *(uint32_t*)(d_Hf + hb + c) = pack_h2(v0, v1);
                    }
                } else {
                    const float g = d_gate[base + m];
                    const size_t yb = (size_t)(base + m) * DMODEL;
#pragma unroll
                    for (int nf = 0; nf < 4; ++nf) {
                        const int c = n0 + wn + nf * 8 + (lid & 3) * 2;
                        const float2 bv = *(const float2*)(bias + (size_t)e * NT + c);
                        float2 o;
                        o.x = g * (acc[mf][nf][hh * 2 + 0] + bv.x);
                        o.y = g * (acc[mf][nf][hh * 2 + 1] + bv.y);
                        *(float2*)(d_Y + yb + c) = o;
                    }
                }
            }
        }
    }
}

// ---------------- combine ----------------
__global__ void combine_kernel(float* __restrict__ out) {
    int t  = blockIdx.x;
    int d4 = threadIdx.x;
    int s0 = d_slot_tk[2 * t];
    int s1 = d_slot_tk[2 * t + 1];
    float4 a = *(const float4*)(d_Y + (size_t)s0 * DMODEL + d4 * 4);
    float4 b = *(const float4*)(d_Y + (size_t)s1 * DMODEL + d4 * 4);
    float4 o;
    o.x = a.x + b.x; o.y = a.y + b.y; o.z = a.z + b.z; o.w = a.w + b.w;
    *(float4*)(out + (size_t)t * DMODEL + d4 * 4) = o;
}

// ---------------- launch ----------------
extern "C" void kernel_launch(void* const* d_in, const int* in_sizes, int n_in,
                              void* d_out, int out_size)
{
    const float* x  = (const float*)d_in[0];
    const float* rw = (const float*)d_in[1];
    const float* rb = (const float*)d_in[2];
    const float* w1 = (const float*)d_in[3];
    const float* b1 = (const float*)d_in[4];
    const float* w2 = (const float*)d_in[5];
    const float* b2 = (const float*)d_in[6];
    float* out = (float*)d_out;

    cudaFuncSetAttribute(gemm_mma<DMODEL, true>,  cudaFuncAttributeMaxDynamicSharedMemorySize, SMEM_BYTES);
    cudaFuncSetAttribute(gemm_mma<DFF,    false>, cudaFuncAttributeMaxDynamicSharedMemorySize, SMEM_BYTES);

    __half* xf;
    cudaGetSymbolAddress((void**)&xf, d_xf);

    zero_counts_kernel<<<1, 32>>>();
    router_kernel<<<T_TOK / 4, 128>>>(x, rw, rb);

    const int nx = T_TOK * DMODEL / 4;
    xcvt_kernel<<<(nx + 255) / 256, 256>>>(x, xf, nx);

    prefix_kernel<<<1, 1>>>();
    scatter_kernel<<<T_TOK / 256, 256>>>();

    gemm_mma<DMODEL, true><<<dim3(DFF / BN, NSLOTS / BM, NEXP), 256, SMEM_BYTES>>>(w1, b1);
    gemm_mma<DFF, false><<<dim3(DMODEL / BN, NSLOTS / BM, NEXP), 256, SMEM_BYTES>>>(w2, b2);

    combine_kernel<<<T_TOK, 128>>>(out);
}

// round 6
// speedup vs baseline: 3.3798x; 1.3273x over previous
#include <cuda_runtime.h>
#include <cuda_fp16.h>
#include <math.h>
#include <stdint.h>

#define T_TOK  4096
#define DMODEL 512
#define DFF    2048
#define NEXP   16
#define TOPK   2
#define NSLOTS (T_TOK*TOPK)

#define BM 128
#define BN 128
#define KC 64            // K elems per stage (64 fp16 = 128B rows)

// smem: 2 stages x (A 16KB + B 16KB) = 64KB
#define OFF_A       0
#define OFF_B       16384
#define STAGE_BYTES 32768
#define SMEM_BYTES  65536

// ---------------- scratch ----------------
__device__ __half d_xf[(size_t)T_TOK * DMODEL];
__device__ __half d_w1f[(size_t)NEXP * DFF * DMODEL];
__device__ __half d_w2f[(size_t)NEXP * DMODEL * DFF];
__device__ __half d_Hf[(size_t)NSLOTS * DFF];
__device__ float d_Y[(size_t)NSLOTS * DMODEL];
__device__ int   d_tok[NSLOTS];
__device__ float d_gate[NSLOTS];
__device__ int   d_slot_tk[NSLOTS];
__device__ int   d_counts[NEXP];
__device__ int   d_off[NEXP];
__device__ int   d_cursor[NEXP];
__device__ int   d_topk_idx[NSLOTS];
__device__ float d_topk_gate[NSLOTS];

// ---------------- PTX helpers ----------------
__device__ __forceinline__ uint32_t smem_u32(const void* p) {
    uint32_t a;
    asm("{ .reg .u64 t; cvta.to.shared.u64 t, %1; cvt.u32.u64 %0, t; }" : "=r"(a) : "l"(p));
    return a;
}
__device__ __forceinline__ uint32_t lds32(uint32_t a) {
    uint32_t v;
    asm volatile("ld.shared.b32 %0, [%1];" : "=r"(v) : "r"(a));
    return v;
}
__device__ __forceinline__ void cpa16(uint32_t dst, const void* src, uint32_t srcsz) {
    asm volatile("cp.async.cg.shared.global [%0], [%1], 16, %2;"
                 :: "r"(dst), "l"(src), "r"(srcsz) : "memory");
}
#define CP_COMMIT() asm volatile("cp.async.commit_group;" ::: "memory")
#define CP_WAIT1()  asm volatile("cp.async.wait_group 1;" ::: "memory")
#define CP_WAIT0()  asm volatile("cp.async.wait_group 0;" ::: "memory")

__device__ __forceinline__ void mma16816(float* d, const uint32_t* a, const uint32_t* b) {
    asm volatile("mma.sync.aligned.m16n8k16.row.col.f32.f16.f16.f32 "
        "{%0,%1,%2,%3}, {%4,%5,%6,%7}, {%8,%9}, {%0,%1,%2,%3};"
        : "+f"(d[0]), "+f"(d[1]), "+f"(d[2]), "+f"(d[3])
        : "r"(a[0]), "r"(a[1]), "r"(a[2]), "r"(a[3]), "r"(b[0]), "r"(b[1]));
}

// pack two floats -> fp16x2 in a u32
__device__ __forceinline__ uint32_t pack_h2(float a, float b) {
    uint32_t r;
    asm("{ .reg .f16 lo, hi; cvt.rn.f16.f32 lo, %1; cvt.rn.f16.f32 hi, %2; mov.b32 %0, {lo, hi}; }"
        : "=r"(r) : "f"(a), "f"(b));
    return r;
}

// SW128 swizzle for 128B-pitch rows
__device__ __forceinline__ uint32_t swz(int row, int cb) {
    return (uint32_t)(row * 128 + (cb ^ ((row & 7) << 4)));
}

// ---------------- small kernels ----------------
__global__ void router_kernel(const float* __restrict__ x,
                              const float* __restrict__ rw,
                              const float* __restrict__ rb)
{
    int warp = (blockIdx.x * blockDim.x + threadIdx.x) >> 5;
    int lane = threadIdx.x & 31;
    if (warp >= T_TOK) return;

    const float* xr = x + (size_t)warp * DMODEL;
    float xv[16];
#pragma unroll
    for (int i = 0; i < 16; i++) xv[i] = xr[lane + 32 * i];

    float lg[NEXP];
#pragma unroll
    for (int e = 0; e < NEXP; e++) {
        const float* wr = rw + e * DMODEL;
        float p = 0.f;
#pragma unroll
        for (int i = 0; i < 16; i++) p = fmaf(xv[i], wr[lane + 32 * i], p);
#pragma unroll
        for (int o = 16; o; o >>= 1) p += __shfl_xor_sync(0xffffffffu, p, o);
        lg[e] = p + rb[e];
    }

    if (lane == 0) {
        float mx = lg[0];
#pragma unroll
        for (int e = 1; e < NEXP; e++) mx = fmaxf(mx, lg[e]);
        float pe[NEXP]; float s = 0.f;
#pragma unroll
        for (int e = 0; e < NEXP; e++) { pe[e] = expf(lg[e] - mx); s += pe[e]; }

        int i1 = 0; float v1 = pe[0];
#pragma unroll
        for (int e = 1; e < NEXP; e++) if (pe[e] > v1) { v1 = pe[e]; i1 = e; }
        int i2 = (i1 == 0) ? 1 : 0; float v2 = pe[i2];
#pragma unroll
        for (int e = 0; e < NEXP; e++)
            if (e != i1 && e != ((i1 == 0) ? 1 : 0) && pe[e] > v2) { v2 = pe[e]; i2 = e; }

        float inv = 1.f / s;
        d_topk_idx[2 * warp]      = i1;
        d_topk_gate[2 * warp]     = v1 * inv;
        d_topk_idx[2 * warp + 1]  = i2;
        d_topk_gate[2 * warp + 1] = v2 * inv;
        atomicAdd(&d_counts[i1], 1);
        atomicAdd(&d_counts[i2], 1);
    }
}

__global__ void prefix_kernel() {
    int s = 0;
#pragma unroll
    for (int e = 0; e < NEXP; e++) { d_off[e] = s; d_cursor[e] = s; s += d_counts[e]; }
}

__global__ void scatter_kernel() {
    int t = blockIdx.x * blockDim.x + threadIdx.x;
    if (t >= T_TOK) return;
#pragma unroll
    for (int k = 0; k < TOPK; k++) {
        int e = d_topk_idx[2 * t + k];
        int slot = atomicAdd(&d_cursor[e], 1);
        d_tok[slot]  = t;
        d_gate[slot] = d_topk_gate[2 * t + k];
        d_slot_tk[2 * t + k] = slot;
    }
}

// x fp32 -> fp16 (+ zero expert counters from block 0)
__global__ void xcvt_kernel(const float* __restrict__ x, int n4) {
    int i = blockIdx.x * blockDim.x + threadIdx.x;
    if (blockIdx.x == 0 && threadIdx.x < NEXP) d_counts[threadIdx.x] = 0;
    if (i >= n4) return;
    float4 v = ((const float4*)x)[i];
    uint32_t* o = (uint32_t*)d_xf;
    o[2 * i]     = pack_h2(v.x, v.y);
    o[2 * i + 1] = pack_h2(v.z, v.w);
}

// w1+w2 fp32 -> fp16, grid-stride over both
__global__ void wcvt_kernel(const float* __restrict__ w1, const float* __restrict__ w2) {
    const int n4_1 = NEXP * DFF * DMODEL / 4;
    const int n4_2 = NEXP * DMODEL * DFF / 4;
    uint32_t* o1 = (uint32_t*)d_w1f;
    uint32_t* o2 = (uint32_t*)d_w2f;
    for (int i = blockIdx.x * blockDim.x + threadIdx.x; i < n4_1 + n4_2;
         i += gridDim.x * blockDim.x) {
        const float4 v = (i < n4_1) ? ((const float4*)w1)[i] : ((const float4*)w2)[i - n4_1];
        uint32_t* o = (i < n4_1) ? (o1 + 2 * i) : (o2 + 2 * (i - n4_1));
        o[0] = pack_h2(v.x, v.y);
        o[1] = pack_h2(v.z, v.w);
    }
}

// ---------------- fp16 HMMA grouped GEMM (cp.async A+B, true 2-stage pipeline) ----------------
template<int KTOT, bool PHASE1>
__global__ __launch_bounds__(256)
void gemm_mma(const float* __restrict__ bias)
{
    constexpr int NT = PHASE1 ? DFF : DMODEL;
    constexpr int NK = KTOT / KC;
    const int e   = blockIdx.z;
    const int cnt = d_counts[e];
    const int m0  = blockIdx.y * BM;
    if (m0 >= cnt) return;
    const int n0   = blockIdx.x * BN;
    const int base = d_off[e];

    extern __shared__ __align__(128) char smem[];
    const uint32_t su = smem_u32(smem);

    const int tid = threadIdx.x;
    const int wid = tid >> 5;
    const int lid = tid & 31;

    // ---- staging roles: thread -> row r, 32-elem half ----
    const int r    = tid >> 1;
    const int half = tid & 1;
    const int gm   = m0 + r;
    const __half* arow = d_xf;
    uint32_t aszA = 0;
    if (gm < cnt) {
        int row = PHASE1 ? d_tok[base + gm] : (base + gm);
        arow = (PHASE1 ? d_xf : d_Hf) + (size_t)row * KTOT;
        aszA = 16;
    }
    const __half* brow = (PHASE1 ? d_w1f : d_w2f) + ((size_t)e * NT + n0 + r) * KTOT;

    uint32_t dstc[4];
#pragma unroll
    for (int j = 0; j < 4; j++) dstc[j] = swz(r, half * 64 + j * 16);

    // ---- compute layout ----
    const int wm  = (wid & 1) * 64;
    const int wn  = (wid >> 1) * 32;
    const int lr  = lid >> 2;
    const int lc4 = (lid & 3) * 4;

    float acc[4][4][4];
#pragma unroll
    for (int i = 0; i < 4; i++)
#pragma unroll
        for (int j = 0; j < 4; j++)
#pragma unroll
            for (int q = 0; q < 4; q++) acc[i][j][q] = 0.f;

    auto issue = [&](int it, int buf) {
        const uint32_t sa = su + (uint32_t)buf * STAGE_BYTES + OFF_A;
        const uint32_t sb = su + (uint32_t)buf * STAGE_BYTES + OFF_B;
        const __half* pa = arow + it * KC + half * 32;
        const __half* pb = brow + it * KC + half * 32;
#pragma unroll
        for (int j = 0; j < 4; j++) {
            cpa16(sa + dstc[j], pa + j * 8, aszA);
            cpa16(sb + dstc[j], pb + j * 8, 16);
        }
    };

    issue(0, 0);
    CP_COMMIT();

    for (int it = 0; it < NK; ++it) {
        const int buf = it & 1;
        if (it + 1 < NK) {
            issue(it + 1, buf ^ 1);
            CP_COMMIT();
            CP_WAIT1();
        } else {
            CP_WAIT0();
        }
        __syncthreads();

        const uint32_t sa  = su + (uint32_t)buf * STAGE_BYTES + OFF_A;
        const uint32_t sbb = su + (uint32_t)buf * STAGE_BYTES + OFF_B;
#pragma unroll
        for (int kk = 0; kk < 4; ++kk) {
            const int kb2 = kk * 32;
            uint32_t Af[4][4], Bf[4][2];
#pragma unroll
            for (int mf = 0; mf < 4; ++mf) {
                const int r0 = wm + mf * 16 + lr;
                Af[mf][0] = lds32(sa + swz(r0,     kb2 + lc4));
                Af[mf][1] = lds32(sa + swz(r0 + 8, kb2 + lc4));
                Af[mf][2] = lds32(sa + swz(r0,     kb2 + lc4 + 16));
                Af[mf][3] = lds32(sa + swz(r0 + 8, kb2 + lc4 + 16));
            }
#pragma unroll
            for (int nf = 0; nf < 4; ++nf) {
                const int rn = wn + nf * 8 + lr;
                Bf[nf][0] = lds32(sbb + swz(rn, kb2 + lc4));
                Bf[nf][1] = lds32(sbb + swz(rn, kb2 + lc4 + 16));
            }
#pragma unroll
            for (int mf = 0; mf < 4; ++mf)
#pragma unroll
                for (int nf = 0; nf < 4; ++nf)
                    mma16816(acc[mf][nf], Af[mf], Bf[nf]);
        }
        __syncthreads();
    }

    // ---- epilogue ----
#pragma unroll
    for (int mf = 0; mf < 4; ++mf) {
        const int mrow = m0 + wm + mf * 16 + lr;
#pragma unroll
        for (int hh = 0; hh < 2; ++hh) {
            const int m = mrow + hh * 8;
            if (m < cnt) {
                if (PHASE1) {
                    const size_t hb = (size_t)(base + m) * DFF;
#pragma unroll
                    for (int nf = 0; nf < 4; ++nf) {
                        const int c = n0 + wn + nf * 8 + (lid & 3) * 2;
                        const float2 bv = *(const float2*)(bias + (size_t)e * NT + c);
                        float v0 = acc[mf][nf][hh * 2 + 0] + bv.x;
                        float v1 = acc[mf][nf][hh * 2 + 1] + bv.y;
                        v0 = 0.5f * v0 * (1.0f + erff(v0 * 0.7071067811865475f));
                        v1 = 0.5f * v1 * (1.0f + erff(v1 * 0.7071067811865475f));
                        *(uint32_t*)(d_Hf + hb + c) = pack_h2(v0, v1);
                    }
                } else {
                    const float g = d_gate[base + m];
                    const size_t yb = (size_t)(base + m) * DMODEL;
#pragma unroll
                    for (int nf = 0; nf < 4; ++nf) {
                        const int c = n0 + wn + nf * 8 + (lid & 3) * 2;
                        const float2 bv = *(const float2*)(bias + (size_t)e * NT + c);
                        float2 o;
                        o.x = g * (acc[mf][nf][hh * 2 + 0] + bv.x);
                        o.y = g * (acc[mf][nf][hh * 2 + 1] + bv.y);
                        *(float2*)(d_Y + yb + c) = o;
                    }
                }
            }
        }
    }
}

// ---------------- combine ----------------
__global__ void combine_kernel(float* __restrict__ out) {
    int t  = blockIdx.x;
    int d4 = threadIdx.x;
    int s0 = d_slot_tk[2 * t];
    int s1 = d_slot_tk[2 * t + 1];
    float4 a = *(const float4*)(d_Y + (size_t)s0 * DMODEL + d4 * 4);
    float4 b = *(const float4*)(d_Y + (size_t)s1 * DMODEL + d4 * 4);
    float4 o;
    o.x = a.x + b.x; o.y = a.y + b.y; o.z = a.z + b.z; o.w = a.w + b.w;
    *(float4*)(out + (size_t)t * DMODEL + d4 * 4) = o;
}

// ---------------- launch ----------------
extern "C" void kernel_launch(void* const* d_in, const int* in_sizes, int n_in,
                              void* d_out, int out_size)
{
    const float* x  = (const float*)d_in[0];
    const float* rw = (const float*)d_in[1];
    const float* rb = (const float*)d_in[2];
    const float* w1 = (const float*)d_in[3];
    const float* b1 = (const float*)d_in[4];
    const float* w2 = (const float*)d_in[5];
    const float* b2 = (const float*)d_in[6];
    float* out = (float*)d_out;

    cudaFuncSetAttribute(gemm_mma<DMODEL, true>,  cudaFuncAttributeMaxDynamicSharedMemorySize, SMEM_BYTES);
    cudaFuncSetAttribute(gemm_mma<DFF,    false>, cudaFuncAttributeMaxDynamicSharedMemorySize, SMEM_BYTES);

    const int nx = T_TOK * DMODEL / 4;
    xcvt_kernel<<<(nx + 255) / 256, 256>>>(x, nx);
    wcvt_kernel<<<2368, 256>>>(w1, w2);
    router_kernel<<<T_TOK / 4, 128>>>(x, rw, rb);
    prefix_kernel<<<1, 1>>>();
    scatter_kernel<<<T_TOK / 256, 256>>>();

    gemm_mma<DMODEL, true><<<dim3(DFF / BN, NSLOTS / BM, NEXP), 256, SMEM_BYTES>>>(b1);
    gemm_mma<DFF, false><<<dim3(DMODEL / BN, NSLOTS / BM, NEXP), 256, SMEM_BYTES>>>(b2);

    combine_kernel<<<T_TOK, 128>>>(out);
}

// round 7
// speedup vs baseline: 4.0036x; 1.1846x over previous
#include <cuda_runtime.h>
#include <cuda_fp16.h>
#include <math.h>
#include <stdint.h>

#define T_TOK  4096
#define DMODEL 512
#define DFF    2048
#define NEXP   16
#define TOPK   2
#define NSLOTS (T_TOK*TOPK)

#define BM 128
#define BN 128
#define KC 64            // K elems per stage (64 fp16 = 128B rows)

// smem: 3 stages x (A 16KB + B 16KB) = 96KB
#define OFF_A       0
#define OFF_B       16384
#define STAGE_BYTES 32768
#define NSTAGE      3
#define SMEM_BYTES  (NSTAGE*STAGE_BYTES)

// ---------------- scratch ----------------
__device__ __half d_xf[(size_t)T_TOK * DMODEL];
__device__ __half d_w1f[(size_t)NEXP * DFF * DMODEL];
__device__ __half d_w2f[(size_t)NEXP * DMODEL * DFF];
__device__ __half d_Hf[(size_t)NSLOTS * DFF];
__device__ float d_Y[(size_t)NSLOTS * DMODEL];
__device__ int   d_tok[NSLOTS];
__device__ float d_gate[NSLOTS];
__device__ int   d_slot_tk[NSLOTS];
__device__ int   d_counts[NEXP];
__device__ int   d_off[NEXP];
__device__ int   d_cursor[NEXP];
__device__ int   d_topk_idx[NSLOTS];
__device__ float d_topk_gate[NSLOTS];

// ---------------- PTX helpers ----------------
__device__ __forceinline__ uint32_t smem_u32(const void* p) {
    uint32_t a;
    asm("{ .reg .u64 t; cvta.to.shared.u64 t, %1; cvt.u32.u64 %0, t; }" : "=r"(a) : "l"(p));
    return a;
}
__device__ __forceinline__ void cpa16(uint32_t dst, const void* src, uint32_t srcsz) {
    asm volatile("cp.async.cg.shared.global [%0], [%1], 16, %2;"
                 :: "r"(dst), "l"(src), "r"(srcsz) : "memory");
}
#define CP_COMMIT() asm volatile("cp.async.commit_group;" ::: "memory")
#define CP_WAIT2()  asm volatile("cp.async.wait_group 2;" ::: "memory")
#define CP_WAIT1()  asm volatile("cp.async.wait_group 1;" ::: "memory")
#define CP_WAIT0()  asm volatile("cp.async.wait_group 0;" ::: "memory")

__device__ __forceinline__ void mma16816(float* d, const uint32_t* a, const uint32_t* b) {
    asm volatile("mma.sync.aligned.m16n8k16.row.col.f32.f16.f16.f32 "
        "{%0,%1,%2,%3}, {%4,%5,%6,%7}, {%8,%9}, {%0,%1,%2,%3};"
        : "+f"(d[0]), "+f"(d[1]), "+f"(d[2]), "+f"(d[3])
        : "r"(a[0]), "r"(a[1]), "r"(a[2]), "r"(a[3]), "r"(b[0]), "r"(b[1]));
}
__device__ __forceinline__ void ldsm4(uint32_t* r, uint32_t addr) {
    asm volatile("ldmatrix.sync.aligned.m8n8.x4.shared.b16 {%0,%1,%2,%3}, [%4];"
        : "=r"(r[0]), "=r"(r[1]), "=r"(r[2]), "=r"(r[3]) : "r"(addr));
}
__device__ __forceinline__ uint32_t pack_h2(float a, float b) {
    uint32_t r;
    asm("{ .reg .f16 lo, hi; cvt.rn.f16.f32 lo, %1; cvt.rn.f16.f32 hi, %2; mov.b32 %0, {lo, hi}; }"
        : "=r"(r) : "f"(a), "f"(b));
    return r;
}

// SW128 swizzle for 128B-pitch rows
__device__ __forceinline__ uint32_t swz(int row, int cb) {
    return (uint32_t)(row * 128 + (cb ^ ((row & 7) << 4)));
}

// ---------------- small kernels ----------------
__global__ void router_kernel(const float* __restrict__ x,
                              const float* __restrict__ rw,
                              const float* __restrict__ rb)
{
    int warp = (blockIdx.x * blockDim.x + threadIdx.x) >> 5;
    int lane = threadIdx.x & 31;
    if (warp >= T_TOK) return;

    const float* xr = x + (size_t)warp * DMODEL;
    float xv[16];
#pragma unroll
    for (int i = 0; i < 16; i++) xv[i] = xr[lane + 32 * i];

    float lg[NEXP];
#pragma unroll
    for (int e = 0; e < NEXP; e++) {
        const float* wr = rw + e * DMODEL;
        float p = 0.f;
#pragma unroll
        for (int i = 0; i < 16; i++) p = fmaf(xv[i], wr[lane + 32 * i], p);
#pragma unroll
        for (int o = 16; o; o >>= 1) p += __shfl_xor_sync(0xffffffffu, p, o);
        lg[e] = p + rb[e];
    }

    if (lane == 0) {
        float mx = lg[0];
#pragma unroll
        for (int e = 1; e < NEXP; e++) mx = fmaxf(mx, lg[e]);
        float pe[NEXP]; float s = 0.f;
#pragma unroll
        for (int e = 0; e < NEXP; e++) { pe[e] = expf(lg[e] - mx); s += pe[e]; }

        int i1 = 0; float v1 = pe[0];
#pragma unroll
        for (int e = 1; e < NEXP; e++) if (pe[e] > v1) { v1 = pe[e]; i1 = e; }
        int i2 = (i1 == 0) ? 1 : 0; float v2 = pe[i2];
#pragma unroll
        for (int e = 0; e < NEXP; e++)
            if (e != i1 && e != ((i1 == 0) ? 1 : 0) && pe[e] > v2) { v2 = pe[e]; i2 = e; }

        float inv = 1.f / s;
        d_topk_idx[2 * warp]      = i1;
        d_topk_gate[2 * warp]     = v1 * inv;
        d_topk_idx[2 * warp + 1]  = i2;
        d_topk_gate[2 * warp + 1] = v2 * inv;
        atomicAdd(&d_counts[i1], 1);
        atomicAdd(&d_counts[i2], 1);
    }
}

__global__ void prefix_kernel() {
    int s = 0;
#pragma unroll
    for (int e = 0; e < NEXP; e++) { d_off[e] = s; d_cursor[e] = s; s += d_counts[e]; }
}

__global__ void scatter_kernel() {
    int t = blockIdx.x * blockDim.x + threadIdx.x;
    if (t >= T_TOK) return;
#pragma unroll
    for (int k = 0; k < TOPK; k++) {
        int e = d_topk_idx[2 * t + k];
        int slot = atomicAdd(&d_cursor[e], 1);
        d_tok[slot]  = t;
        d_gate[slot] = d_topk_gate[2 * t + k];
        d_slot_tk[2 * t + k] = slot;
    }
}

// x fp32 -> fp16 (+ zero expert counters from block 0)
__global__ void xcvt_kernel(const float* __restrict__ x, int n4) {
    int i = blockIdx.x * blockDim.x + threadIdx.x;
    if (blockIdx.x == 0 && threadIdx.x < NEXP) d_counts[threadIdx.x] = 0;
    if (i >= n4) return;
    float4 v = ((const float4*)x)[i];
    uint32_t* o = (uint32_t*)d_xf;
    o[2 * i]     = pack_h2(v.x, v.y);
    o[2 * i + 1] = pack_h2(v.z, v.w);
}

// w1+w2 fp32 -> fp16, grid-stride over both
__global__ void wcvt_kernel(const float* __restrict__ w1, const float* __restrict__ w2) {
    const int n4_1 = NEXP * DFF * DMODEL / 4;
    const int n4_2 = NEXP * DMODEL * DFF / 4;
    uint32_t* o1 = (uint32_t*)d_w1f;
    uint32_t* o2 = (uint32_t*)d_w2f;
    for (int i = blockIdx.x * blockDim.x + threadIdx.x; i < n4_1 + n4_2;
         i += gridDim.x * blockDim.x) {
        const float4 v = (i < n4_1) ? ((const float4*)w1)[i] : ((const float4*)w2)[i - n4_1];
        uint32_t* o = (i < n4_1) ? (o1 + 2 * i) : (o2 + 2 * (i - n4_1));
        o[0] = pack_h2(v.x, v.y);
        o[1] = pack_h2(v.z, v.w);
    }
}

// ---------------- fp16 HMMA grouped GEMM (ldmatrix + 3-stage cp.async) ----------------
template<int KTOT, bool PHASE1>
__global__ __launch_bounds__(256, 2)
void gemm_mma(const float* __restrict__ bias)
{
    constexpr int NT = PHASE1 ? DFF : DMODEL;
    constexpr int NK = KTOT / KC;
    const int e   = blockIdx.z;
    const int cnt = d_counts[e];
    const int m0  = blockIdx.y * BM;
    if (m0 >= cnt) return;
    const int n0   = blockIdx.x * BN;
    const int base = d_off[e];

    extern __shared__ __align__(128) char smem[];
    const uint32_t su = smem_u32(smem);

    const int tid = threadIdx.x;
    const int wid = tid >> 5;
    const int lid = tid & 31;

    // ---- staging roles: thread -> row r, 32-elem half ----
    const int r    = tid >> 1;
    const int half = tid & 1;
    const int gm   = m0 + r;
    const __half* arow = d_xf;
    uint32_t aszA = 0;
    if (gm < cnt) {
        int row = PHASE1 ? d_tok[base + gm] : (base + gm);
        arow = (PHASE1 ? d_xf : d_Hf) + (size_t)row * KTOT;
        aszA = 16;
    }
    const __half* brow = (PHASE1 ? d_w1f : d_w2f) + ((size_t)e * NT + n0 + r) * KTOT;

    uint32_t dstc[4];
#pragma unroll
    for (int j = 0; j < 4; j++) dstc[j] = swz(r, half * 64 + j * 16);

    // ---- compute layout ----
    const int wm  = (wid & 1) * 64;
    const int wn  = (wid >> 1) * 32;
    const int lr  = lid >> 2;

    // ldmatrix per-lane bases
    const int mi    = lid >> 3;                      // matrix index 0..3
    const int rowAl = wm + (mi & 1) * 8 + (lid & 7); // A: +mf*16
    const int cbA   = (mi >> 1) * 16;                // A: +kb2
    const int rowBl = wn + (mi >> 1) * 8 + (lid & 7);// B: +p*16
    const int cbB   = (mi & 1) * 16;                 // B: +kb2

    float acc[4][4][4];
#pragma unroll
    for (int i = 0; i < 4; i++)
#pragma unroll
        for (int j = 0; j < 4; j++)
#pragma unroll
            for (int q = 0; q < 4; q++) acc[i][j][q] = 0.f;

    auto issue = [&](int it, int buf) {
        const uint32_t sa = su + (uint32_t)buf * STAGE_BYTES + OFF_A;
        const uint32_t sb = su + (uint32_t)buf * STAGE_BYTES + OFF_B;
        const __half* pa = arow + it * KC + half * 32;
        const __half* pb = brow + it * KC + half * 32;
#pragma unroll
        for (int j = 0; j < 4; j++) {
            cpa16(sa + dstc[j], pa + j * 8, aszA);
            cpa16(sb + dstc[j], pb + j * 8, 16);
        }
    };

    issue(0, 0); CP_COMMIT();
    issue(1, 1); CP_COMMIT();

    for (int it = 0; it < NK; ++it) {
        const int buf = it % NSTAGE;
        if (it + 2 < NK) {
            issue(it + 2, (it + 2) % NSTAGE);
            CP_COMMIT();
            CP_WAIT2();
        } else if (it + 1 < NK) {
            CP_WAIT1();
        } else {
            CP_WAIT0();
        }
        __syncthreads();

        const uint32_t sa  = su + (uint32_t)buf * STAGE_BYTES + OFF_A;
        const uint32_t sbb = su + (uint32_t)buf * STAGE_BYTES + OFF_B;
#pragma unroll
        for (int kk = 0; kk < 4; ++kk) {
            const int kb2 = kk * 32;
            uint32_t Af[4][4], Bf[4][2];
#pragma unroll
            for (int mf = 0; mf < 4; ++mf)
                ldsm4(Af[mf], sa + swz(rowAl + mf * 16, kb2 + cbA));
#pragma unroll
            for (int p = 0; p < 2; ++p) {
                uint32_t br[4];
                ldsm4(br, sbb + swz(rowBl + p * 16, kb2 + cbB));
                Bf[2 * p][0]     = br[0]; Bf[2 * p][1]     = br[1];
                Bf[2 * p + 1][0] = br[2]; Bf[2 * p + 1][1] = br[3];
            }
#pragma unroll
            for (int mf = 0; mf < 4; ++mf)
#pragma unroll
                for (int nf = 0; nf < 4; ++nf)
                    mma16816(acc[mf][nf], Af[mf], Bf[nf]);
        }
        __syncthreads();
    }

    // ---- epilogue ----
#pragma unroll
    for (int mf = 0; mf < 4; ++mf) {
        const int mrow = m0 + wm + mf * 16 + lr;
#pragma unroll
        for (int hh = 0; hh < 2; ++hh) {
            const int m = mrow + hh * 8;
            if (m < cnt) {
                if (PHASE1) {
                    const size_t hb = (size_t)(base + m) * DFF;
#pragma unroll
                    for (int nf = 0; nf < 4; ++nf) {
                        const int c = n0 + wn + nf * 8 + (lid & 3) * 2;
                        const float2 bv = *(const float2*)(bias + (size_t)e * NT + c);
                        float v0 = acc[mf][nf][hh * 2 + 0] + bv.x;
                        float v1 = acc[mf][nf][hh * 2 + 1] + bv.y;
                        v0 = 0.5f * v0 * (1.0f + erff(v0 * 0.7071067811865475f));
                        v1 = 0.5f * v1 * (1.0f + erff(v1 * 0.7071067811865475f));
                        *(uint32_t*)(d_Hf + hb + c) = pack_h2(v0, v1);
                    }
                } else {
                    const float g = d_gate[base + m];
                    const size_t yb = (size_t)(base + m) * DMODEL;
#pragma unroll
                    for (int nf = 0; nf < 4; ++nf) {
                        const int c = n0 + wn + nf * 8 + (lid & 3) * 2;
                        const float2 bv = *(const float2*)(bias + (size_t)e * NT + c);
                        float2 o;
                        o.x = g * (acc[mf][nf][hh * 2 + 0] + bv.x);
                        o.y = g * (acc[mf][nf][hh * 2 + 1] + bv.y);
                        *(float2*)(d_Y + yb + c) = o;
                    }
                }
            }
        }
    }
}

// ---------------- combine ----------------
__global__ void combine_kernel(float* __restrict__ out) {
    int t  = blockIdx.x;
    int d4 = threadIdx.x;
    int s0 = d_slot_tk[2 * t];
    int s1 = d_slot_tk[2 * t + 1];
    float4 a = *(const float4*)(d_Y + (size_t)s0 * DMODEL + d4 * 4);
    float4 b = *(const float4*)(d_Y + (size_t)s1 * DMODEL + d4 * 4);
    float4 o;
    o.x = a.x + b.x; o.y = a.y + b.y; o.z = a.z + b.z; o.w = a.w + b.w;
    *(float4*)(out + (size_t)t * DMODEL + d4 * 4) = o;
}

// ---------------- launch ----------------
extern "C" void kernel_launch(void* const* d_in, const int* in_sizes, int n_in,
                              void* d_out, int out_size)
{
    const float* x  = (const float*)d_in[0];
    const float* rw = (const float*)d_in[1];
    const float* rb = (const float*)d_in[2];
    const float* w1 = (const float*)d_in[3];
    const float* b1 = (const float*)d_in[4];
    const float* w2 = (const float*)d_in[5];
    const float* b2 = (const float*)d_in[6];
    float* out = (float*)d_out;

    cudaFuncSetAttribute(gemm_mma<DMODEL, true>,  cudaFuncAttributeMaxDynamicSharedMemorySize, SMEM_BYTES);
    cudaFuncSetAttribute(gemm_mma<DFF,    false>, cudaFuncAttributeMaxDynamicSharedMemorySize, SMEM_BYTES);

    const int nx = T_TOK * DMODEL / 4;
    xcvt_kernel<<<(nx + 255) / 256, 256>>>(x, nx);
    wcvt_kernel<<<2368, 256>>>(w1, w2);
    router_kernel<<<T_TOK / 4, 128>>>(x, rw, rb);
    prefix_kernel<<<1, 1>>>();
    scatter_kernel<<<T_TOK / 256, 256>>>();

    gemm_mma<DMODEL, true><<<dim3(DFF / BN, NSLOTS / BM, NEXP), 256, SMEM_BYTES>>>(b1);
    gemm_mma<DFF, false><<<dim3(DMODEL / BN, NSLOTS / BM, NEXP), 256, SMEM_BYTES>>>(b2);

    combine_kernel<<<T_TOK, 128>>>(out);
}

// round 8
// speedup vs baseline: 4.1239x; 1.0300x over previous
#include <cuda_runtime.h>
#include <cuda_fp16.h>
#include <math.h>
#include <stdint.h>

#define T_TOK  4096
#define DMODEL 512
#define DFF    2048
#define NEXP   16
#define TOPK   2
#define NSLOTS (T_TOK*TOPK)

#define BM 128
#define BN 128
#define KC 64            // K elems per stage (64 fp16 = 128B rows)

// smem: 3 stages x (A 16KB + B 16KB) = 96KB
#define OFF_A       0
#define OFF_B       16384
#define STAGE_BYTES 32768
#define NSTAGE      3
#define SMEM_BYTES  (NSTAGE*STAGE_BYTES)

// ---------------- scratch ----------------
__device__ __half d_xf[(size_t)T_TOK * DMODEL];
__device__ __half d_w1f[(size_t)NEXP * DFF * DMODEL];
__device__ __half d_w2f[(size_t)NEXP * DMODEL * DFF];
__device__ __half d_Hf[(size_t)NSLOTS * DFF];
__device__ float d_Y[(size_t)NSLOTS * DMODEL];
__device__ int   d_tok[NSLOTS];
__device__ float d_gate[NSLOTS];
__device__ int   d_slot_tk[NSLOTS];
__device__ int   d_counts[NEXP];
__device__ int   d_off[NEXP];
__device__ int   d_cursor[NEXP];
__device__ int   d_topk_idx[NSLOTS];
__device__ float d_topk_gate[NSLOTS];

// ---------------- PTX helpers ----------------
__device__ __forceinline__ uint32_t smem_u32(const void* p) {
    uint32_t a;
    asm("{ .reg .u64 t; cvta.to.shared.u64 t, %1; cvt.u32.u64 %0, t; }" : "=r"(a) : "l"(p));
    return a;
}
__device__ __forceinline__ void cpa16(uint32_t dst, const void* src, uint32_t srcsz) {
    asm volatile("cp.async.cg.shared.global [%0], [%1], 16, %2;"
                 :: "r"(dst), "l"(src), "r"(srcsz) : "memory");
}
#define CP_COMMIT() asm volatile("cp.async.commit_group;" ::: "memory")
#define CP_WAIT1()  asm volatile("cp.async.wait_group 1;" ::: "memory")
#define CP_WAIT0()  asm volatile("cp.async.wait_group 0;" ::: "memory")

__device__ __forceinline__ void mma16816(float* d, const uint32_t* a, const uint32_t* b) {
    asm volatile("mma.sync.aligned.m16n8k16.row.col.f32.f16.f16.f32 "
        "{%0,%1,%2,%3}, {%4,%5,%6,%7}, {%8,%9}, {%0,%1,%2,%3};"
        : "+f"(d[0]), "+f"(d[1]), "+f"(d[2]), "+f"(d[3])
        : "r"(a[0]), "r"(a[1]), "r"(a[2]), "r"(a[3]), "r"(b[0]), "r"(b[1]));
}
__device__ __forceinline__ void ldsm4(uint32_t* r, uint32_t addr) {
    asm volatile("ldmatrix.sync.aligned.m8n8.x4.shared.b16 {%0,%1,%2,%3}, [%4];"
        : "=r"(r[0]), "=r"(r[1]), "=r"(r[2]), "=r"(r[3]) : "r"(addr));
}
__device__ __forceinline__ uint32_t pack_h2(float a, float b) {
    uint32_t r;
    asm("{ .reg .f16 lo, hi; cvt.rn.f16.f32 lo, %1; cvt.rn.f16.f32 hi, %2; mov.b32 %0, {lo, hi}; }"
        : "=r"(r) : "f"(a), "f"(b));
    return r;
}

// SW128 swizzle for 128B-pitch rows
__device__ __forceinline__ uint32_t swz(int row, int cb) {
    return (uint32_t)(row * 128 + (cb ^ ((row & 7) << 4)));
}

// ---------------- router (+ fused x fp32->fp16 conversion) ----------------
__global__ void router_kernel(const float* __restrict__ x,
                              const float* __restrict__ rw,
                              const float* __restrict__ rb)
{
    int warp = (blockIdx.x * blockDim.x + threadIdx.x) >> 5;
    int lane = threadIdx.x & 31;
    if (warp >= T_TOK) return;

    const float* xr = x + (size_t)warp * DMODEL;
    float xv[16];
#pragma unroll
    for (int i = 0; i < 16; i++) xv[i] = xr[lane + 32 * i];

    // fused conversion: this warp owns token row `warp`
    {
        uint32_t* xo = (uint32_t*)(d_xf + (size_t)warp * DMODEL);
#pragma unroll
        for (int i = 0; i < 16; i += 2) {
            // elements lane+32i and lane+32(i+1) are not adjacent; store scalars
            __half h0 = __float2half_rn(xv[i]);
            __half h1 = __float2half_rn(xv[i + 1]);
            d_xf[(size_t)warp * DMODEL + lane + 32 * i]       = h0;
            d_xf[(size_t)warp * DMODEL + lane + 32 * (i + 1)] = h1;
        }
        (void)xo;
    }

    float lg[NEXP];
#pragma unroll
    for (int e = 0; e < NEXP; e++) {
        const float* wr = rw + e * DMODEL;
        float p = 0.f;
#pragma unroll
        for (int i = 0; i < 16; i++) p = fmaf(xv[i], wr[lane + 32 * i], p);
#pragma unroll
        for (int o = 16; o; o >>= 1) p += __shfl_xor_sync(0xffffffffu, p, o);
        lg[e] = p + rb[e];
    }

    if (lane == 0) {
        float mx = lg[0];
#pragma unroll
        for (int e = 1; e < NEXP; e++) mx = fmaxf(mx, lg[e]);
        float pe[NEXP]; float s = 0.f;
#pragma unroll
        for (int e = 0; e < NEXP; e++) { pe[e] = expf(lg[e] - mx); s += pe[e]; }

        int i1 = 0; float v1 = pe[0];
#pragma unroll
        for (int e = 1; e < NEXP; e++) if (pe[e] > v1) { v1 = pe[e]; i1 = e; }
        int i2 = (i1 == 0) ? 1 : 0; float v2 = pe[i2];
#pragma unroll
        for (int e = 0; e < NEXP; e++)
            if (e != i1 && e != ((i1 == 0) ? 1 : 0) && pe[e] > v2) { v2 = pe[e]; i2 = e; }

        float inv = 1.f / s;
        d_topk_idx[2 * warp]      = i1;
        d_topk_gate[2 * warp]     = v1 * inv;
        d_topk_idx[2 * warp + 1]  = i2;
        d_topk_gate[2 * warp + 1] = v2 * inv;
        atomicAdd(&d_counts[i1], 1);
        atomicAdd(&d_counts[i2], 1);
    }
}

// fused prefix + scatter: single block, 1024 threads
__global__ void prefix_scatter_kernel() {
    if (threadIdx.x == 0) {
        int s = 0;
#pragma unroll
        for (int e = 0; e < NEXP; e++) { d_off[e] = s; d_cursor[e] = s; s += d_counts[e]; }
    }
    __syncthreads();
    for (int t = threadIdx.x; t < T_TOK; t += blockDim.x) {
#pragma unroll
        for (int k = 0; k < TOPK; k++) {
            int e = d_topk_idx[2 * t + k];
            int slot = atomicAdd(&d_cursor[e], 1);
            d_tok[slot]  = t;
            d_gate[slot] = d_topk_gate[2 * t + k];
            d_slot_tk[2 * t + k] = slot;
        }
    }
}

// w1+w2 fp32 -> fp16, grid-stride over both (+ zero expert counters)
__global__ void wcvt_kernel(const float* __restrict__ w1, const float* __restrict__ w2) {
    if (blockIdx.x == 0 && threadIdx.x < NEXP) d_counts[threadIdx.x] = 0;
    const int n4_1 = NEXP * DFF * DMODEL / 4;
    const int n4_2 = NEXP * DMODEL * DFF / 4;
    uint32_t* o1 = (uint32_t*)d_w1f;
    uint32_t* o2 = (uint32_t*)d_w2f;
    for (int i = blockIdx.x * blockDim.x + threadIdx.x; i < n4_1 + n4_2;
         i += gridDim.x * blockDim.x) {
        const float4 v = (i < n4_1) ? ((const float4*)w1)[i] : ((const float4*)w2)[i - n4_1];
        uint32_t* o = (i < n4_1) ? (o1 + 2 * i) : (o2 + 2 * (i - n4_1));
        o[0] = pack_h2(v.x, v.y);
        o[1] = pack_h2(v.z, v.w);
    }
}

// ---------------- fp16 HMMA grouped GEMM (ldmatrix + 3-stage, 1 sync/iter) ----------------
template<int KTOT, bool PHASE1>
__global__ __launch_bounds__(256, 2)
void gemm_mma(const float* __restrict__ bias)
{
    constexpr int NT = PHASE1 ? DFF : DMODEL;
    constexpr int NK = KTOT / KC;
    const int e   = blockIdx.z;
    const int cnt = d_counts[e];
    const int m0  = blockIdx.y * BM;
    if (m0 >= cnt) return;
    const int n0   = blockIdx.x * BN;
    const int base = d_off[e];

    extern __shared__ __align__(128) char smem[];
    const uint32_t su = smem_u32(smem);

    const int tid = threadIdx.x;
    const int wid = tid >> 5;
    const int lid = tid & 31;

    // ---- staging roles: thread -> row r, 32-elem half ----
    const int r    = tid >> 1;
    const int half = tid & 1;
    const int gm   = m0 + r;
    const __half* arow = d_xf;
    uint32_t aszA = 0;
    if (gm < cnt) {
        int row = PHASE1 ? d_tok[base + gm] : (base + gm);
        arow = (PHASE1 ? d_xf : d_Hf) + (size_t)row * KTOT;
        aszA = 16;
    }
    const __half* brow = (PHASE1 ? d_w1f : d_w2f) + ((size_t)e * NT + n0 + r) * KTOT;

    uint32_t dstc[4];
#pragma unroll
    for (int j = 0; j < 4; j++) dstc[j] = swz(r, half * 64 + j * 16);

    // ---- compute layout ----
    const int wm  = (wid & 1) * 64;
    const int wn  = (wid >> 1) * 32;
    const int lr  = lid >> 2;

    // ldmatrix per-lane bases
    const int mi    = lid >> 3;
    const int rowAl = wm + (mi & 1) * 8 + (lid & 7);
    const int cbA   = (mi >> 1) * 16;
    const int rowBl = wn + (mi >> 1) * 8 + (lid & 7);
    const int cbB   = (mi & 1) * 16;

    float acc[4][4][4];
#pragma unroll
    for (int i = 0; i < 4; i++)
#pragma unroll
        for (int j = 0; j < 4; j++)
#pragma unroll
            for (int q = 0; q < 4; q++) acc[i][j][q] = 0.f;

    auto issue = [&](int it, int buf) {
        const uint32_t sa = su + (uint32_t)buf * STAGE_BYTES + OFF_A;
        const uint32_t sb = su + (uint32_t)buf * STAGE_BYTES + OFF_B;
        const __half* pa = arow + it * KC + half * 32;
        const __half* pb = brow + it * KC + half * 32;
#pragma unroll
        for (int j = 0; j < 4; j++) {
            cpa16(sa + dstc[j], pa + j * 8, aszA);
            cpa16(sb + dstc[j], pb + j * 8, 16);
        }
    };

    issue(0, 0); CP_COMMIT();
    issue(1, 1); CP_COMMIT();

    for (int it = 0; it < NK; ++it) {
        const int buf = it % NSTAGE;
        if (it + 1 < NK) CP_WAIT1(); else CP_WAIT0();
        __syncthreads();
        if (it + 2 < NK) {
            issue(it + 2, (it + 2) % NSTAGE);
            CP_COMMIT();
        }

        const uint32_t sa  = su + (uint32_t)buf * STAGE_BYTES + OFF_A;
        const uint32_t sbb = su + (uint32_t)buf * STAGE_BYTES + OFF_B;
#pragma unroll
        for (int kk = 0; kk < 4; ++kk) {
            const int kb2 = kk * 32;
            uint32_t Af[4][4], Bf[4][2];
#pragma unroll
            for (int mf = 0; mf < 4; ++mf)
                ldsm4(Af[mf], sa + swz(rowAl + mf * 16, kb2 + cbA));
#pragma unroll
            for (int p = 0; p < 2; ++p) {
                uint32_t br[4];
                ldsm4(br, sbb + swz(rowBl + p * 16, kb2 + cbB));
                Bf[2 * p][0]     = br[0]; Bf[2 * p][1]     = br[1];
                Bf[2 * p + 1][0] = br[2]; Bf[2 * p + 1][1] = br[3];
            }
#pragma unroll
            for (int mf = 0; mf < 4; ++mf)
#pragma unroll
                for (int nf = 0; nf < 4; ++nf)
                    mma16816(acc[mf][nf], Af[mf], Bf[nf]);
        }
    }

    // ---- epilogue ----
#pragma unroll
    for (int mf = 0; mf < 4; ++mf) {
        const int mrow = m0 + wm + mf * 16 + lr;
#pragma unroll
        for (int hh = 0; hh < 2; ++hh) {
            const int m = mrow + hh * 8;
            if (m < cnt) {
                if (PHASE1) {
                    const size_t hb = (size_t)(base + m) * DFF;
#pragma unroll
                    for (int nf = 0; nf < 4; ++nf) {
                        const int c = n0 + wn + nf * 8 + (lid & 3) * 2;
                        const float2 bv = *(const float2*)(bias + (size_t)e * NT + c);
                        float v0 = acc[mf][nf][hh * 2 + 0] + bv.x;
                        float v1 = acc[mf][nf][hh * 2 + 1] + bv.y;
                        v0 = 0.5f * v0 * (1.0f + erff(v0 * 0.7071067811865475f));
                        v1 = 0.5f * v1 * (1.0f + erff(v1 * 0.7071067811865475f));
                        *(uint32_t*)(d_Hf + hb + c) = pack_h2(v0, v1);
                    }
                } else {
                    const float g = d_gate[base + m];
                    const size_t yb = (size_t)(base + m) * DMODEL;
#pragma unroll
                    for (int nf = 0; nf < 4; ++nf) {
                        const int c = n0 + wn + nf * 8 + (lid & 3) * 2;
                        const float2 bv = *(const float2*)(bias + (size_t)e * NT + c);
                        float2 o;
                        o.x = g * (acc[mf][nf][hh * 2 + 0] + bv.x);
                        o.y = g * (acc[mf][nf][hh * 2 + 1] + bv.y);
                        *(float2*)(d_Y + yb + c) = o;
                    }
                }
            }
        }
    }
}

// ---------------- combine ----------------
__global__ void combine_kernel(float* __restrict__ out) {
    int t  = blockIdx.x;
    int d4 = threadIdx.x;
    int s0 = d_slot_tk[2 * t];
    int s1 = d_slot_tk[2 * t + 1];
    float4 a = *(const float4*)(d_Y + (size_t)s0 * DMODEL + d4 * 4);
    float4 b = *(const float4*)(d_Y + (size_t)s1 * DMODEL + d4 * 4);
    float4 o;
    o.x = a.x + b.x; o.y = a.y + b.y; o.z = a.z + b.z; o.w = a.w + b.w;
    *(float4*)(out + (size_t)t * DMODEL + d4 * 4) = o;
}

// ---------------- launch ----------------
extern "C" void kernel_launch(void* const* d_in, const int* in_sizes, int n_in,
                              void* d_out, int out_size)
{
    const float* x  = (const float*)d_in[0];
    const float* rw = (const float*)d_in[1];
    const float* rb = (const float*)d_in[2];
    const float* w1 = (const float*)d_in[3];
    const float* b1 = (const float*)d_in[4];
    const float* w2 = (const float*)d_in[5];
    const float* b2 = (const float*)d_in[6];
    float* out = (float*)d_out;

    cudaFuncSetAttribute(gemm_mma<DMODEL, true>,  cudaFuncAttributeMaxDynamicSharedMemorySize, SMEM_BYTES);
    cudaFuncSetAttribute(gemm_mma<DFF,    false>, cudaFuncAttributeMaxDynamicSharedMemorySize, SMEM_BYTES);

    wcvt_kernel<<<2368, 256>>>(w1, w2);
    router_kernel<<<T_TOK / 4, 128>>>(x, rw, rb);
    prefix_scatter_kernel<<<1, 1024>>>();

    gemm_mma<DMODEL, true><<<dim3(DFF / BN, NSLOTS / BM, NEXP), 256, SMEM_BYTES>>>(b1);
    gemm_mma<DFF, false><<<dim3(DMODEL / BN, NSLOTS / BM, NEXP), 256, SMEM_BYTES>>>(b2);

    combine_kernel<<<T_TOK, 128>>>(out);
}

// round 9
// speedup vs baseline: 4.4194x; 1.0717x over previous
#include <cuda_runtime.h>
#include <cuda_fp16.h>
#include <math.h>
#include <stdint.h>

#define T_TOK  4096
#define DMODEL 512
#define DFF    2048
#define NEXP   16
#define TOPK   2
#define NSLOTS (T_TOK*TOPK)

#define BM 128
#define BN 128
#define KC 64            // K elems per stage (64 fp16 = 128B rows)
#define MAXMT (NSLOTS/BM + NEXP)   // max live m-tiles = 80

// smem: 3 stages x (A 16KB + B 16KB) = 96KB
#define OFF_A       0
#define OFF_B       16384
#define STAGE_BYTES 32768
#define NSTAGE      3
#define SMEM_BYTES  (NSTAGE*STAGE_BYTES)

// ---------------- scratch ----------------
__device__ __half d_xf[(size_t)T_TOK * DMODEL];
__device__ __half d_w1f[(size_t)NEXP * DFF * DMODEL];
__device__ __half d_w2f[(size_t)NEXP * DMODEL * DFF];
__device__ __half d_Hf[(size_t)NSLOTS * DFF];
__device__ float d_Y[(size_t)NSLOTS * DMODEL];
__device__ int   d_tok[NSLOTS];
__device__ float d_gate[NSLOTS];
__device__ int   d_slot_tk[NSLOTS];
__device__ int   d_counts[NEXP];
__device__ int   d_off[NEXP];
__device__ int   d_cursor[NEXP];
__device__ int   d_topk_idx[NSLOTS];
__device__ float d_topk_gate[NSLOTS];
__device__ uint32_t d_mtile[MAXMT];   // (e<<16)|m0
__device__ int   d_nmt;

// ---------------- PTX helpers ----------------
__device__ __forceinline__ uint32_t smem_u32(const void* p) {
    uint32_t a;
    asm("{ .reg .u64 t; cvta.to.shared.u64 t, %1; cvt.u32.u64 %0, t; }" : "=r"(a) : "l"(p));
    return a;
}
__device__ __forceinline__ void cpa16(uint32_t dst, const void* src, uint32_t srcsz) {
    asm volatile("cp.async.cg.shared.global [%0], [%1], 16, %2;"
                 :: "r"(dst), "l"(src), "r"(srcsz) : "memory");
}
#define CP_COMMIT() asm volatile("cp.async.commit_group;" ::: "memory")
#define CP_WAIT1()  asm volatile("cp.async.wait_group 1;" ::: "memory")
#define CP_WAIT0()  asm volatile("cp.async.wait_group 0;" ::: "memory")

__device__ __forceinline__ void mma16816(float* d, const uint32_t* a, const uint32_t* b) {
    asm volatile("mma.sync.aligned.m16n8k16.row.col.f32.f16.f16.f32 "
        "{%0,%1,%2,%3}, {%4,%5,%6,%7}, {%8,%9}, {%0,%1,%2,%3};"
        : "+f"(d[0]), "+f"(d[1]), "+f"(d[2]), "+f"(d[3])
        : "r"(a[0]), "r"(a[1]), "r"(a[2]), "r"(a[3]), "r"(b[0]), "r"(b[1]));
}
__device__ __forceinline__ void ldsm4(uint32_t* r, uint32_t addr) {
    asm volatile("ldmatrix.sync.aligned.m8n8.x4.shared.b16 {%0,%1,%2,%3}, [%4];"
        : "=r"(r[0]), "=r"(r[1]), "=r"(r[2]), "=r"(r[3]) : "r"(addr));
}
__device__ __forceinline__ uint32_t pack_h2(float a, float b) {
    uint32_t r;
    asm("{ .reg .f16 lo, hi; cvt.rn.f16.f32 lo, %1; cvt.rn.f16.f32 hi, %2; mov.b32 %0, {lo, hi}; }"
        : "=r"(r) : "f"(a), "f"(b));
    return r;
}

// SW128 swizzle for 128B-pitch rows
__device__ __forceinline__ uint32_t swz(int row, int cb) {
    return (uint32_t)(row * 128 + (cb ^ ((row & 7) << 4)));
}

// ---------------- router (+ fused x fp32->fp16 conversion) ----------------
__global__ void router_kernel(const float* __restrict__ x,
                              const float* __restrict__ rw,
                              const float* __restrict__ rb)
{
    int warp = (blockIdx.x * blockDim.x + threadIdx.x) >> 5;
    int lane = threadIdx.x & 31;
    if (warp >= T_TOK) return;

    const float* xr = x + (size_t)warp * DMODEL;
    float xv[16];
#pragma unroll
    for (int i = 0; i < 16; i++) xv[i] = xr[lane + 32 * i];

    // fused conversion: this warp owns token row `warp`
#pragma unroll
    for (int i = 0; i < 16; i++)
        d_xf[(size_t)warp * DMODEL + lane + 32 * i] = __float2half_rn(xv[i]);

    float lg[NEXP];
#pragma unroll
    for (int e = 0; e < NEXP; e++) {
        const float* wr = rw + e * DMODEL;
        float p = 0.f;
#pragma unroll
        for (int i = 0; i < 16; i++) p = fmaf(xv[i], wr[lane + 32 * i], p);
#pragma unroll
        for (int o = 16; o; o >>= 1) p += __shfl_xor_sync(0xffffffffu, p, o);
        lg[e] = p + rb[e];
    }

    if (lane == 0) {
        float mx = lg[0];
#pragma unroll
        for (int e = 1; e < NEXP; e++) mx = fmaxf(mx, lg[e]);
        float pe[NEXP]; float s = 0.f;
#pragma unroll
        for (int e = 0; e < NEXP; e++) { pe[e] = expf(lg[e] - mx); s += pe[e]; }

        int i1 = 0; float v1 = pe[0];
#pragma unroll
        for (int e = 1; e < NEXP; e++) if (pe[e] > v1) { v1 = pe[e]; i1 = e; }
        int i2 = (i1 == 0) ? 1 : 0; float v2 = pe[i2];
#pragma unroll
        for (int e = 0; e < NEXP; e++)
            if (e != i1 && e != ((i1 == 0) ? 1 : 0) && pe[e] > v2) { v2 = pe[e]; i2 = e; }

        float inv = 1.f / s;
        d_topk_idx[2 * warp]      = i1;
        d_topk_gate[2 * warp]     = v1 * inv;
        d_topk_idx[2 * warp + 1]  = i2;
        d_topk_gate[2 * warp + 1] = v2 * inv;
        atomicAdd(&d_counts[i1], 1);
        atomicAdd(&d_counts[i2], 1);
    }
}

// fused prefix + scatter + m-tile worklist: single block, 1024 threads
__global__ void prefix_scatter_kernel() {
    if (threadIdx.x == 0) {
        int s = 0, nm = 0;
#pragma unroll
        for (int e = 0; e < NEXP; e++) {
            d_off[e] = s; d_cursor[e] = s;
            const int c = d_counts[e];
            for (int m0 = 0; m0 < c; m0 += BM)
                d_mtile[nm++] = ((uint32_t)e << 16) | (uint32_t)m0;
            s += c;
        }
        d_nmt = nm;
    }
    __syncthreads();
    for (int t = threadIdx.x; t < T_TOK; t += blockDim.x) {
#pragma unroll
        for (int k = 0; k < TOPK; k++) {
            int e = d_topk_idx[2 * t + k];
            int slot = atomicAdd(&d_cursor[e], 1);
            d_tok[slot]  = t;
            d_gate[slot] = d_topk_gate[2 * t + k];
            d_slot_tk[2 * t + k] = slot;
        }
    }
}

// w1+w2 fp32 -> fp16, grid-stride over both (+ zero expert counters)
__global__ void wcvt_kernel(const float* __restrict__ w1, const float* __restrict__ w2) {
    if (blockIdx.x == 0 && threadIdx.x < NEXP) d_counts[threadIdx.x] = 0;
    const int n4_1 = NEXP * DFF * DMODEL / 4;
    const int n4_2 = NEXP * DMODEL * DFF / 4;
    uint32_t* o1 = (uint32_t*)d_w1f;
    uint32_t* o2 = (uint32_t*)d_w2f;
    for (int i = blockIdx.x * blockDim.x + threadIdx.x; i < n4_1 + n4_2;
         i += gridDim.x * blockDim.x) {
        const float4 v = (i < n4_1) ? ((const float4*)w1)[i] : ((const float4*)w2)[i - n4_1];
        uint32_t* o = (i < n4_1) ? (o1 + 2 * i) : (o2 + 2 * (i - n4_1));
        o[0] = pack_h2(v.x, v.y);
        o[1] = pack_h2(v.z, v.w);
    }
}

// ---------------- fp16 HMMA grouped GEMM (worklist-driven) ----------------
template<int KTOT, bool PHASE1>
__global__ __launch_bounds__(256, 2)
void gemm_mma(const float* __restrict__ bias)
{
    constexpr int NT = PHASE1 ? DFF : DMODEL;
    constexpr int NK = KTOT / KC;
    if ((int)blockIdx.y >= d_nmt) return;
    const uint32_t mt = d_mtile[blockIdx.y];
    const int e   = (int)(mt >> 16);
    const int m0  = (int)(mt & 0xffffu);
    const int cnt = d_counts[e];
    const int n0   = blockIdx.x * BN;
    const int base = d_off[e];

    extern __shared__ __align__(128) char smem[];
    const uint32_t su = smem_u32(smem);

    const int tid = threadIdx.x;
    const int wid = tid >> 5;
    const int lid = tid & 31;

    // ---- staging roles: thread -> row r, 32-elem half ----
    const int r    = tid >> 1;
    const int half = tid & 1;
    const int gm   = m0 + r;
    const __half* arow = d_xf;
    uint32_t aszA = 0;
    if (gm < cnt) {
        int row = PHASE1 ? d_tok[base + gm] : (base + gm);
        arow = (PHASE1 ? d_xf : d_Hf) + (size_t)row * KTOT;
        aszA = 16;
    }
    const __half* brow = (PHASE1 ? d_w1f : d_w2f) + ((size_t)e * NT + n0 + r) * KTOT;

    uint32_t dstc[4];
#pragma unroll
    for (int j = 0; j < 4; j++) dstc[j] = swz(r, half * 64 + j * 16);

    // ---- compute layout ----
    const int wm  = (wid & 1) * 64;
    const int wn  = (wid >> 1) * 32;
    const int lr  = lid >> 2;

    // ldmatrix per-lane bases
    const int mi    = lid >> 3;
    const int rowAl = wm + (mi & 1) * 8 + (lid & 7);
    const int cbA   = (mi >> 1) * 16;
    const int rowBl = wn + (mi >> 1) * 8 + (lid & 7);
    const int cbB   = (mi & 1) * 16;

    float acc[4][4][4];
#pragma unroll
    for (int i = 0; i < 4; i++)
#pragma unroll
        for (int j = 0; j < 4; j++)
#pragma unroll
            for (int q = 0; q < 4; q++) acc[i][j][q] = 0.f;

    auto issue = [&](int it, int buf) {
        const uint32_t sa = su + (uint32_t)buf * STAGE_BYTES + OFF_A;
        const uint32_t sb = su + (uint32_t)buf * STAGE_BYTES + OFF_B;
        const __half* pa = arow + it * KC + half * 32;
        const __half* pb = brow + it * KC + half * 32;
#pragma unroll
        for (int j = 0; j < 4; j++) {
            cpa16(sa + dstc[j], pa + j * 8, aszA);
            cpa16(sb + dstc[j], pb + j * 8, 16);
        }
    };

    issue(0, 0); CP_COMMIT();
    issue(1, 1); CP_COMMIT();

    for (int it = 0; it < NK; ++it) {
        const int buf = it % NSTAGE;
        if (it + 1 < NK) CP_WAIT1(); else CP_WAIT0();
        __syncthreads();
        if (it + 2 < NK) {
            issue(it + 2, (it + 2) % NSTAGE);
            CP_COMMIT();
        }

        const uint32_t sa  = su + (uint32_t)buf * STAGE_BYTES + OFF_A;
        const uint32_t sbb = su + (uint32_t)buf * STAGE_BYTES + OFF_B;
#pragma unroll
        for (int kk = 0; kk < 4; ++kk) {
            const int kb2 = kk * 32;
            uint32_t Af[4][4], Bf[4][2];
#pragma unroll
            for (int mf = 0; mf < 4; ++mf)
                ldsm4(Af[mf], sa + swz(rowAl + mf * 16, kb2 + cbA));
#pragma unroll
            for (int p = 0; p < 2; ++p) {
                uint32_t br[4];
                ldsm4(br, sbb + swz(rowBl + p * 16, kb2 + cbB));
                Bf[2 * p][0]     = br[0]; Bf[2 * p][1]     = br[1];
                Bf[2 * p + 1][0] = br[2]; Bf[2 * p + 1][1] = br[3];
            }
#pragma unroll
            for (int mf = 0; mf < 4; ++mf)
#pragma unroll
                for (int nf = 0; nf < 4; ++nf)
                    mma16816(acc[mf][nf], Af[mf], Bf[nf]);
        }
    }

    // ---- epilogue ----
#pragma unroll
    for (int mf = 0; mf < 4; ++mf) {
        const int mrow = m0 + wm + mf * 16 + lr;
#pragma unroll
        for (int hh = 0; hh < 2; ++hh) {
            const int m = mrow + hh * 8;
            if (m < cnt) {
                if (PHASE1) {
                    const size_t hb = (size_t)(base + m) * DFF;
#pragma unroll
                    for (int nf = 0; nf < 4; ++nf) {
                        const int c = n0 + wn + nf * 8 + (lid & 3) * 2;
                        const float2 bv = *(const float2*)(bias + (size_t)e * NT + c);
                        float v0 = acc[mf][nf][hh * 2 + 0] + bv.x;
                        float v1 = acc[mf][nf][hh * 2 + 1] + bv.y;
                        v0 = 0.5f * v0 * (1.0f + erff(v0 * 0.7071067811865475f));
                        v1 = 0.5f * v1 * (1.0f + erff(v1 * 0.7071067811865475f));
                        *(uint32_t*)(d_Hf + hb + c) = pack_h2(v0, v1);
                    }
                } else {
                    const float g = d_gate[base + m];
                    const size_t yb = (size_t)(base + m) * DMODEL;
#pragma unroll
                    for (int nf = 0; nf < 4; ++nf) {
                        const int c = n0 + wn + nf * 8 + (lid & 3) * 2;
                        const float2 bv = *(const float2*)(bias + (size_t)e * NT + c);
                        float2 o;
                        o.x = g * (acc[mf][nf][hh * 2 + 0] + bv.x);
                        o.y = g * (acc[mf][nf][hh * 2 + 1] + bv.y);
                        *(float2*)(d_Y + yb + c) = o;
                    }
                }
            }
        }
    }
}

// ---------------- combine ----------------
__global__ void combine_kernel(float* __restrict__ out) {
    int t  = blockIdx.x;
    int d4 = threadIdx.x;
    int s0 = d_slot_tk[2 * t];
    int s1 = d_slot_tk[2 * t + 1];
    float4 a = *(const float4*)(d_Y + (size_t)s0 * DMODEL + d4 * 4);
    float4 b = *(const float4*)(d_Y + (size_t)s1 * DMODEL + d4 * 4);
    float4 o;
    o.x = a.x + b.x; o.y = a.y + b.y; o.z = a.z + b.z; o.w = a.w + b.w;
    *(float4*)(out + (size_t)t * DMODEL + d4 * 4) = o;
}

// ---------------- launch ----------------
extern "C" void kernel_launch(void* const* d_in, const int* in_sizes, int n_in,
                              void* d_out, int out_size)
{
    const float* x  = (const float*)d_in[0];
    const float* rw = (const float*)d_in[1];
    const float* rb = (const float*)d_in[2];
    const float* w1 = (const float*)d_in[3];
    const float* b1 = (const float*)d_in[4];
    const float* w2 = (const float*)d_in[5];
    const float* b2 = (const float*)d_in[6];
    float* out = (float*)d_out;

    cudaFuncSetAttribute(gemm_mma<DMODEL, true>,  cudaFuncAttributeMaxDynamicSharedMemorySize, SMEM_BYTES);
    cudaFuncSetAttribute(gemm_mma<DFF,    false>, cudaFuncAttributeMaxDynamicSharedMemorySize, SMEM_BYTES);

    wcvt_kernel<<<2368, 256>>>(w1, w2);
    router_kernel<<<T_TOK / 4, 128>>>(x, rw, rb);
    prefix_scatter_kernel<<<1, 1024>>>();

    gemm_mma<DMODEL, true><<<dim3(DFF / BN, MAXMT), 256, SMEM_BYTES>>>(b1);
    gemm_mma<DFF, false><<<dim3(DMODEL / BN, MAXMT), 256, SMEM_BYTES>>>(b2);

    combine_kernel<<<T_TOK, 128>>>(out);
}

// round 10
// speedup vs baseline: 4.7305x; 1.0704x over previous
#include <cuda_runtime.h>
#include <cuda_fp16.h>
#include <math.h>
#include <stdint.h>

#define T_TOK  4096
#define DMODEL 512
#define DFF    2048
#define NEXP   16
#define TOPK   2
#define NSLOTS (T_TOK*TOPK)

#define BM 128
#define BN 128
#define KC 64            // K elems per stage (64 fp16 = 128B rows)
#define MAXMT (NSLOTS/BM + NEXP)   // max live m-tiles = 80

// smem: 3 stages x (A 16KB + B 16KB) = 96KB
#define OFF_A       0
#define OFF_B       16384
#define STAGE_BYTES 32768
#define NSTAGE      3
#define SMEM_BYTES  (NSTAGE*STAGE_BYTES)

// ---------------- scratch ----------------
__device__ __half d_xf[(size_t)T_TOK * DMODEL];
__device__ __half d_w1f[(size_t)NEXP * DFF * DMODEL];
__device__ __half d_w2f[(size_t)NEXP * DMODEL * DFF];
__device__ __half d_Hf[(size_t)NSLOTS * DFF];
__device__ float d_Y[(size_t)NSLOTS * DMODEL];
__device__ int   d_tok[NSLOTS];
__device__ float d_gate[NSLOTS];
__device__ int   d_slot_tk[NSLOTS];
__device__ int   d_counts[NEXP];
__device__ int   d_off[NEXP];
__device__ int   d_cursor[NEXP];
__device__ int   d_topk_idx[NSLOTS];
__device__ float d_topk_gate[NSLOTS];
__device__ uint32_t d_mtile[MAXMT];   // (e<<16)|m0
__device__ int   d_nmt;

// ---------------- PTX helpers ----------------
__device__ __forceinline__ uint32_t smem_u32(const void* p) {
    uint32_t a;
    asm("{ .reg .u64 t; cvta.to.shared.u64 t, %1; cvt.u32.u64 %0, t; }" : "=r"(a) : "l"(p));
    return a;
}
__device__ __forceinline__ void cpa16(uint32_t dst, const void* src, uint32_t srcsz) {
    asm volatile("cp.async.cg.shared.global [%0], [%1], 16, %2;"
                 :: "r"(dst), "l"(src), "r"(srcsz) : "memory");
}
#define CP_COMMIT() asm volatile("cp.async.commit_group;" ::: "memory")
#define CP_WAIT1()  asm volatile("cp.async.wait_group 1;" ::: "memory")
#define CP_WAIT0()  asm volatile("cp.async.wait_group 0;" ::: "memory")

__device__ __forceinline__ void mma16816(float* d, const uint32_t* a, const uint32_t* b) {
    asm volatile("mma.sync.aligned.m16n8k16.row.col.f32.f16.f16.f32 "
        "{%0,%1,%2,%3}, {%4,%5,%6,%7}, {%8,%9}, {%0,%1,%2,%3};"
        : "+f"(d[0]), "+f"(d[1]), "+f"(d[2]), "+f"(d[3])
        : "r"(a[0]), "r"(a[1]), "r"(a[2]), "r"(a[3]), "r"(b[0]), "r"(b[1]));
}
__device__ __forceinline__ void ldsm4(uint32_t* r, uint32_t addr) {
    asm volatile("ldmatrix.sync.aligned.m8n8.x4.shared.b16 {%0,%1,%2,%3}, [%4];"
        : "=r"(r[0]), "=r"(r[1]), "=r"(r[2]), "=r"(r[3]) : "r"(addr));
}
__device__ __forceinline__ uint32_t pack_h2(float a, float b) {
    uint32_t r;
    asm("{ .reg .f16 lo, hi; cvt.rn.f16.f32 lo, %1; cvt.rn.f16.f32 hi, %2; mov.b32 %0, {lo, hi}; }"
        : "=r"(r) : "f"(a), "f"(b));
    return r;
}

// SW128 swizzle for 128B-pitch rows
__device__ __forceinline__ uint32_t swz(int row, int cb) {
    return (uint32_t)(row * 128 + (cb ^ ((row & 7) << 4)));
}

// ---------------- router (+ fused x fp32->fp16 conversion) ----------------
__global__ void router_kernel(const float* __restrict__ x,
                              const float* __restrict__ rw,
                              const float* __restrict__ rb)
{
    int warp = (blockIdx.x * blockDim.x + threadIdx.x) >> 5;
    int lane = threadIdx.x & 31;
    if (warp >= T_TOK) return;

    const float* xr = x + (size_t)warp * DMODEL;
    float xv[16];
#pragma unroll
    for (int i = 0; i < 16; i++) xv[i] = xr[lane + 32 * i];

#pragma unroll
    for (int i = 0; i < 16; i++)
        d_xf[(size_t)warp * DMODEL + lane + 32 * i] = __float2half_rn(xv[i]);

    float lg[NEXP];
#pragma unroll
    for (int e = 0; e < NEXP; e++) {
        const float* wr = rw + e * DMODEL;
        float p = 0.f;
#pragma unroll
        for (int i = 0; i < 16; i++) p = fmaf(xv[i], wr[lane + 32 * i], p);
#pragma unroll
        for (int o = 16; o; o >>= 1) p += __shfl_xor_sync(0xffffffffu, p, o);
        lg[e] = p + rb[e];
    }

    if (lane == 0) {
        float mx = lg[0];
#pragma unroll
        for (int e = 1; e < NEXP; e++) mx = fmaxf(mx, lg[e]);
        float pe[NEXP]; float s = 0.f;
#pragma unroll
        for (int e = 0; e < NEXP; e++) { pe[e] = expf(lg[e] - mx); s += pe[e]; }

        int i1 = 0; float v1 = pe[0];
#pragma unroll
        for (int e = 1; e < NEXP; e++) if (pe[e] > v1) { v1 = pe[e]; i1 = e; }
        int i2 = (i1 == 0) ? 1 : 0; float v2 = pe[i2];
#pragma unroll
        for (int e = 0; e < NEXP; e++)
            if (e != i1 && e != ((i1 == 0) ? 1 : 0) && pe[e] > v2) { v2 = pe[e]; i2 = e; }

        float inv = 1.f / s;
        d_topk_idx[2 * warp]      = i1;
        d_topk_gate[2 * warp]     = v1 * inv;
        d_topk_idx[2 * warp + 1]  = i2;
        d_topk_gate[2 * warp + 1] = v2 * inv;
        atomicAdd(&d_counts[i1], 1);
        atomicAdd(&d_counts[i2], 1);
    }
}

// fused prefix + scatter + m-tile worklist
__global__ void prefix_scatter_kernel() {
    if (threadIdx.x == 0) {
        int s = 0, nm = 0;
#pragma unroll
        for (int e = 0; e < NEXP; e++) {
            d_off[e] = s; d_cursor[e] = s;
            const int c = d_counts[e];
            for (int m0 = 0; m0 < c; m0 += BM)
                d_mtile[nm++] = ((uint32_t)e << 16) | (uint32_t)m0;
            s += c;
        }
        d_nmt = nm;
    }
    __syncthreads();
    for (int t = threadIdx.x; t < T_TOK; t += blockDim.x) {
#pragma unroll
        for (int k = 0; k < TOPK; k++) {
            int e = d_topk_idx[2 * t + k];
            int slot = atomicAdd(&d_cursor[e], 1);
            d_tok[slot]  = t;
            d_gate[slot] = d_topk_gate[2 * t + k];
            d_slot_tk[2 * t + k] = slot;
        }
    }
}

// w1+w2 fp32 -> fp16 (+ zero expert counters)
__global__ void wcvt_kernel(const float* __restrict__ w1, const float* __restrict__ w2) {
    if (blockIdx.x == 0 && threadIdx.x < NEXP) d_counts[threadIdx.x] = 0;
    const int n4_1 = NEXP * DFF * DMODEL / 4;
    const int n4_2 = NEXP * DMODEL * DFF / 4;
    uint32_t* o1 = (uint32_t*)d_w1f;
    uint32_t* o2 = (uint32_t*)d_w2f;
    for (int i = blockIdx.x * blockDim.x + threadIdx.x; i < n4_1 + n4_2;
         i += gridDim.x * blockDim.x) {
        const float4 v = (i < n4_1) ? ((const float4*)w1)[i] : ((const float4*)w2)[i - n4_1];
        uint32_t* o = (i < n4_1) ? (o1 + 2 * i) : (o2 + 2 * (i - n4_1));
        o[0] = pack_h2(v.x, v.y);
        o[1] = pack_h2(v.z, v.w);
    }
}

// ---------------- fp16 HMMA grouped GEMM (fragment-pipelined) ----------------
template<int KTOT, bool PHASE1>
__global__ __launch_bounds__(256, 2)
void gemm_mma(const float* __restrict__ bias)
{
    constexpr int NT = PHASE1 ? DFF : DMODEL;
    constexpr int NK = KTOT / KC;
    if ((int)blockIdx.y >= d_nmt) return;
    const uint32_t mt = d_mtile[blockIdx.y];
    const int e   = (int)(mt >> 16);
    const int m0  = (int)(mt & 0xffffu);
    const int cnt = d_counts[e];
    const int n0   = blockIdx.x * BN;
    const int base = d_off[e];

    extern __shared__ __align__(128) char smem[];
    const uint32_t su = smem_u32(smem);

    const int tid = threadIdx.x;
    const int wid = tid >> 5;
    const int lid = tid & 31;

    // ---- staging roles ----
    const int r    = tid >> 1;
    const int half = tid & 1;
    const int gm   = m0 + r;
    const __half* arow = d_xf;
    uint32_t aszA = 0;
    if (gm < cnt) {
        int row = PHASE1 ? d_tok[base + gm] : (base + gm);
        arow = (PHASE1 ? d_xf : d_Hf) + (size_t)row * KTOT;
        aszA = 16;
    }
    const __half* brow = (PHASE1 ? d_w1f : d_w2f) + ((size_t)e * NT + n0 + r) * KTOT;

    uint32_t dstc[4];
#pragma unroll
    for (int j = 0; j < 4; j++) dstc[j] = swz(r, half * 64 + j * 16);

    // ---- compute layout ----
    const int wm  = (wid & 1) * 64;
    const int wn  = (wid >> 1) * 32;
    const int lr  = lid >> 2;

    const int mi    = lid >> 3;
    const int rowAl = wm + (mi & 1) * 8 + (lid & 7);
    const int cbA   = (mi >> 1) * 16;
    const int rowBl = wn + (mi >> 1) * 8 + (lid & 7);
    const int cbB   = (mi & 1) * 16;

    float acc[4][4][4];
#pragma unroll
    for (int i = 0; i < 4; i++)
#pragma unroll
        for (int j = 0; j < 4; j++)
#pragma unroll
            for (int q = 0; q < 4; q++) acc[i][j][q] = 0.f;

    auto issue = [&](int it, int buf) {
        const uint32_t sa = su + (uint32_t)buf * STAGE_BYTES + OFF_A;
        const uint32_t sb = su + (uint32_t)buf * STAGE_BYTES + OFF_B;
        const __half* pa = arow + it * KC + half * 32;
        const __half* pb = brow + it * KC + half * 32;
#pragma unroll
        for (int j = 0; j < 4; j++) {
            cpa16(sa + dstc[j], pa + j * 8, aszA);
            cpa16(sb + dstc[j], pb + j * 8, 16);
        }
    };

    // fragment double buffers
    uint32_t Afr[2][16], Bfr[2][8];

    auto ldfrag = [&](uint32_t sa, uint32_t sbb, int kb2, uint32_t* A, uint32_t* B) {
#pragma unroll
        for (int mf = 0; mf < 4; ++mf)
            ldsm4(A + mf * 4, sa + swz(rowAl + mf * 16, kb2 + cbA));
#pragma unroll
        for (int p = 0; p < 2; ++p)
            ldsm4(B + p * 4, sbb + swz(rowBl + p * 16, kb2 + cbB));
    };

    issue(0, 0); CP_COMMIT();
    issue(1, 1); CP_COMMIT();
    CP_WAIT1();
    __syncthreads();
    ldfrag(su + OFF_A, su + OFF_B, 0, Afr[0], Bfr[0]);

    for (int it = 0; it < NK; ++it) {
        const int buf = it % NSTAGE;
        const uint32_t sa  = su + (uint32_t)buf * STAGE_BYTES + OFF_A;
        const uint32_t sbb = su + (uint32_t)buf * STAGE_BYTES + OFF_B;
#pragma unroll
        for (int kk = 0; kk < 4; ++kk) {
            const int cur = kk & 1;
            if (kk < 3) {
                ldfrag(sa, sbb, (kk + 1) * 32, Afr[cur ^ 1], Bfr[cur ^ 1]);
            } else if (it + 1 < NK) {
                if (it + 2 < NK) {
                    issue(it + 2, (it + 2) % NSTAGE);
                    CP_COMMIT();
                    CP_WAIT1();
                } else {
                    CP_WAIT0();
                }
                __syncthreads();
                const int nbuf = (it + 1) % NSTAGE;
                ldfrag(su + (uint32_t)nbuf * STAGE_BYTES + OFF_A,
                       su + (uint32_t)nbuf * STAGE_BYTES + OFF_B,
                       0, Afr[cur ^ 1], Bfr[cur ^ 1]);
            }
#pragma unroll
            for (int mf = 0; mf < 4; ++mf)
#pragma unroll
                for (int nf = 0; nf < 4; ++nf)
                    mma16816(acc[mf][nf], Afr[cur] + mf * 4, Bfr[cur] + nf * 2);
        }
    }

    // ---- epilogue ----
#pragma unroll
    for (int mf = 0; mf < 4; ++mf) {
        const int mrow = m0 + wm + mf * 16 + lr;
#pragma unroll
        for (int hh = 0; hh < 2; ++hh) {
            const int m = mrow + hh * 8;
            if (m < cnt) {
                if (PHASE1) {
                    const size_t hb = (size_t)(base + m) * DFF;
#pragma unroll
                    for (int nf = 0; nf < 4; ++nf) {
                        const int c = n0 + wn + nf * 8 + (lid & 3) * 2;
                        const float2 bv = *(const float2*)(bias + (size_t)e * NT + c);
                        float v0 = acc[mf][nf][hh * 2 + 0] + bv.x;
                        float v1 = acc[mf][nf][hh * 2 + 1] + bv.y;
                        v0 = 0.5f * v0 * (1.0f + erff(v0 * 0.7071067811865475f));
                        v1 = 0.5f * v1 * (1.0f + erff(v1 * 0.7071067811865475f));
                        *(uint32_t*)(d_Hf + hb + c) = pack_h2(v0, v1);
                    }
                } else {
                    const float g = d_gate[base + m];
                    const size_t yb = (size_t)(base + m) * DMODEL;
#pragma unroll
                    for (int nf = 0; nf < 4; ++nf) {
                        const int c = n0 + wn + nf * 8 + (lid & 3) * 2;
                        const float2 bv = *(const float2*)(bias + (size_t)e * NT + c);
                        float2 o;
                        o.x = g * (acc[mf][nf][hh * 2 + 0] + bv.x);
                        o.y = g * (acc[mf][nf][hh * 2 + 1] + bv.y);
                        *(float2*)(d_Y + yb + c) = o;
                    }
                }
            }
        }
    }
}

// ---------------- combine ----------------
__global__ void combine_kernel(float* __restrict__ out) {
    int t  = blockIdx.x;
    int d4 = threadIdx.x;
    int s0 = d_slot_tk[2 * t];
    int s1 = d_slot_tk[2 * t + 1];
    float4 a = *(const float4*)(d_Y + (size_t)s0 * DMODEL + d4 * 4);
    float4 b = *(const float4*)(d_Y + (size_t)s1 * DMODEL + d4 * 4);
    float4 o;
    o.x = a.x + b.x; o.y = a.y + b.y; o.z = a.z + b.z; o.w = a.w + b.w;
    *(float4*)(out + (size_t)t * DMODEL + d4 * 4) = o;
}

// ---------------- launch ----------------
extern "C" void kernel_launch(void* const* d_in, const int* in_sizes, int n_in,
                              void* d_out, int out_size)
{
    const float* x  = (const float*)d_in[0];
    const float* rw = (const float*)d_in[1];
    const float* rb = (const float*)d_in[2];
    const float* w1 = (const float*)d_in[3];
    const float* b1 = (const float*)d_in[4];
    const float* w2 = (const float*)d_in[5];
    const float* b2 = (const float*)d_in[6];
    float* out = (float*)d_out;

    cudaFuncSetAttribute(gemm_mma<DMODEL, true>,  cudaFuncAttributeMaxDynamicSharedMemorySize, SMEM_BYTES);
    cudaFuncSetAttribute(gemm_mma<DFF,    false>, cudaFuncAttributeMaxDynamicSharedMemorySize, SMEM_BYTES);

    wcvt_kernel<<<2368, 256>>>(w1, w2);
    router_kernel<<<T_TOK / 4, 128>>>(x, rw, rb);
    prefix_scatter_kernel<<<1, 1024>>>();

    gemm_mma<DMODEL, true><<<dim3(DFF / BN, MAXMT), 256, SMEM_BYTES>>>(b1);
    gemm_mma<DFF, false><<<dim3(DMODEL / BN, MAXMT), 256, SMEM_BYTES>>>(b2);

    combine_kernel<<<T_TOK, 128>>>(out);
}

// round 11
// speedup vs baseline: 4.9459x; 1.0455x over previous
#include <cuda_runtime.h>
#include <cuda_fp16.h>
#include <math.h>
#include <stdint.h>

#define T_TOK  4096
#define DMODEL 512
#define DFF    2048
#define NEXP   16
#define TOPK   2
#define NSLOTS (T_TOK*TOPK)

#define BM 128
#define BN 128
#define KC 64            // K elems per stage (64 fp16 = 128B rows)
#define MAXMT (NSLOTS/BM + NEXP)   // max live m-tiles = 80

// smem: 3 stages x (A 16KB + B 16KB) = 96KB
#define OFF_A       0
#define OFF_B       16384
#define STAGE_BYTES 32768
#define NSTAGE      3
#define SMEM_BYTES  (NSTAGE*STAGE_BYTES)

// ---------------- scratch ----------------
__device__ __half d_xf[(size_t)T_TOK * DMODEL];
__device__ __half d_w1f[(size_t)NEXP * DFF * DMODEL];
__device__ __half d_w2f[(size_t)NEXP * DMODEL * DFF];
__device__ __half d_Hf[(size_t)NSLOTS * DFF];
__device__ float d_Y[(size_t)NSLOTS * DMODEL];
__device__ int   d_tok[NSLOTS];
__device__ float d_gate[NSLOTS];
__device__ int   d_slot_tk[NSLOTS];
__device__ int   d_counts[NEXP];
__device__ int   d_off[NEXP];
__device__ int   d_topk_idx[NSLOTS];
__device__ float d_topk_gate[NSLOTS];
__device__ uint32_t d_mtile[MAXMT];   // (e<<16)|m0
__device__ int   d_nmt;

// ---------------- PTX helpers ----------------
__device__ __forceinline__ uint32_t smem_u32(const void* p) {
    uint32_t a;
    asm("{ .reg .u64 t; cvta.to.shared.u64 t, %1; cvt.u32.u64 %0, t; }" : "=r"(a) : "l"(p));
    return a;
}
__device__ __forceinline__ void cpa16(uint32_t dst, const void* src, uint32_t srcsz) {
    asm volatile("cp.async.cg.shared.global [%0], [%1], 16, %2;"
                 :: "r"(dst), "l"(src), "r"(srcsz) : "memory");
}
#define CP_COMMIT() asm volatile("cp.async.commit_group;" ::: "memory")
#define CP_WAIT1()  asm volatile("cp.async.wait_group 1;" ::: "memory")
#define CP_WAIT0()  asm volatile("cp.async.wait_group 0;" ::: "memory")

__device__ __forceinline__ void mma16816(float* d, const uint32_t* a, const uint32_t* b) {
    asm volatile("mma.sync.aligned.m16n8k16.row.col.f32.f16.f16.f32 "
        "{%0,%1,%2,%3}, {%4,%5,%6,%7}, {%8,%9}, {%0,%1,%2,%3};"
        : "+f"(d[0]), "+f"(d[1]), "+f"(d[2]), "+f"(d[3])
        : "r"(a[0]), "r"(a[1]), "r"(a[2]), "r"(a[3]), "r"(b[0]), "r"(b[1]));
}
__device__ __forceinline__ void ldsm4(uint32_t* r, uint32_t addr) {
    asm volatile("ldmatrix.sync.aligned.m8n8.x4.shared.b16 {%0,%1,%2,%3}, [%4];"
        : "=r"(r[0]), "=r"(r[1]), "=r"(r[2]), "=r"(r[3]) : "r"(addr));
}
__device__ __forceinline__ uint32_t pack_h2(float a, float b) {
    uint32_t r;
    asm("{ .reg .f16 lo, hi; cvt.rn.f16.f32 lo, %1; cvt.rn.f16.f32 hi, %2; mov.b32 %0, {lo, hi}; }"
        : "=r"(r) : "f"(a), "f"(b));
    return r;
}

// SW128 swizzle for 128B-pitch rows
__device__ __forceinline__ uint32_t swz(int row, int cb) {
    return (uint32_t)(row * 128 + (cb ^ ((row & 7) << 4)));
}

// ---------------- router (+ fused x fp32->fp16 conversion; NO atomics) ----------------
__global__ void router_kernel(const float* __restrict__ x,
                              const float* __restrict__ rw,
                              const float* __restrict__ rb)
{
    int warp = (blockIdx.x * blockDim.x + threadIdx.x) >> 5;
    int lane = threadIdx.x & 31;
    if (warp >= T_TOK) return;

    const float* xr = x + (size_t)warp * DMODEL;
    float xv[16];
#pragma unroll
    for (int i = 0; i < 16; i++) xv[i] = xr[lane + 32 * i];

#pragma unroll
    for (int i = 0; i < 16; i++)
        d_xf[(size_t)warp * DMODEL + lane + 32 * i] = __float2half_rn(xv[i]);

    float lg[NEXP];
#pragma unroll
    for (int e = 0; e < NEXP; e++) {
        const float* wr = rw + e * DMODEL;
        float p = 0.f;
#pragma unroll
        for (int i = 0; i < 16; i++) p = fmaf(xv[i], wr[lane + 32 * i], p);
#pragma unroll
        for (int o = 16; o; o >>= 1) p += __shfl_xor_sync(0xffffffffu, p, o);
        lg[e] = p + rb[e];
    }

    if (lane == 0) {
        float mx = lg[0];
#pragma unroll
        for (int e = 1; e < NEXP; e++) mx = fmaxf(mx, lg[e]);
        float pe[NEXP]; float s = 0.f;
#pragma unroll
        for (int e = 0; e < NEXP; e++) { pe[e] = expf(lg[e] - mx); s += pe[e]; }

        int i1 = 0; float v1 = pe[0];
#pragma unroll
        for (int e = 1; e < NEXP; e++) if (pe[e] > v1) { v1 = pe[e]; i1 = e; }
        int i2 = (i1 == 0) ? 1 : 0; float v2 = pe[i2];
#pragma unroll
        for (int e = 0; e < NEXP; e++)
            if (e != i1 && e != ((i1 == 0) ? 1 : 0) && pe[e] > v2) { v2 = pe[e]; i2 = e; }

        float inv = 1.f / s;
        d_topk_idx[2 * warp]      = i1;
        d_topk_gate[2 * warp]     = v1 * inv;
        d_topk_idx[2 * warp + 1]  = i2;
        d_topk_gate[2 * warp + 1] = v2 * inv;
    }
}

// histogram + prefix + m-tile worklist + scatter, all in one block (smem atomics)
__global__ void prefix_scatter_kernel() {
    __shared__ int hist[NEXP];
    __shared__ int scur[NEXP];
    if (threadIdx.x < NEXP) hist[threadIdx.x] = 0;
    __syncthreads();
    for (int i = threadIdx.x; i < NSLOTS; i += blockDim.x)
        atomicAdd(&hist[d_topk_idx[i]], 1);
    __syncthreads();
    if (threadIdx.x == 0) {
        int s = 0, nm = 0;
#pragma unroll
        for (int e = 0; e < NEXP; e++) {
            const int c = hist[e];
            d_off[e] = s; scur[e] = s; d_counts[e] = c;
            for (int m0 = 0; m0 < c; m0 += BM)
                d_mtile[nm++] = ((uint32_t)e << 16) | (uint32_t)m0;
            s += c;
        }
        d_nmt = nm;
    }
    __syncthreads();
    for (int t = threadIdx.x; t < T_TOK; t += blockDim.x) {
#pragma unroll
        for (int k = 0; k < TOPK; k++) {
            int e = d_topk_idx[2 * t + k];
            int slot = atomicAdd(&scur[e], 1);
            d_tok[slot]  = t;
            d_gate[slot] = d_topk_gate[2 * t + k];
            d_slot_tk[2 * t + k] = slot;
        }
    }
}

// w1 fp32 -> fp16
__global__ void wcvt1_kernel(const float* __restrict__ w1) {
    const int n4 = NEXP * DFF * DMODEL / 4;
    uint32_t* o = (uint32_t*)d_w1f;
    for (int i = blockIdx.x * blockDim.x + threadIdx.x; i < n4; i += gridDim.x * blockDim.x) {
        const float4 v = ((const float4*)w1)[i];
        o[2 * i]     = pack_h2(v.x, v.y);
        o[2 * i + 1] = pack_h2(v.z, v.w);
    }
}
// w2 fp32 -> fp16
__global__ void wcvt2_kernel(const float* __restrict__ w2) {
    const int n4 = NEXP * DMODEL * DFF / 4;
    uint32_t* o = (uint32_t*)d_w2f;
    for (int i = blockIdx.x * blockDim.x + threadIdx.x; i < n4; i += gridDim.x * blockDim.x) {
        const float4 v = ((const float4*)w2)[i];
        o[2 * i]     = pack_h2(v.x, v.y);
        o[2 * i + 1] = pack_h2(v.z, v.w);
    }
}

// ---------------- fp16 HMMA grouped GEMM (fragment-pipelined, worklist-driven) ----------------
template<int KTOT, bool PHASE1>
__global__ __launch_bounds__(256, 2)
void gemm_mma(const float* __restrict__ bias)
{
    constexpr int NT = PHASE1 ? DFF : DMODEL;
    constexpr int NK = KTOT / KC;
    if ((int)blockIdx.y >= d_nmt) return;
    const uint32_t mt = d_mtile[blockIdx.y];
    const int e   = (int)(mt >> 16);
    const int m0  = (int)(mt & 0xffffu);
    const int cnt = d_counts[e];
    const int n0   = blockIdx.x * BN;
    const int base = d_off[e];

    extern __shared__ __align__(128) char smem[];
    const uint32_t su = smem_u32(smem);

    const int tid = threadIdx.x;
    const int wid = tid >> 5;
    const int lid = tid & 31;

    // ---- staging roles ----
    const int r    = tid >> 1;
    const int half = tid & 1;
    const int gm   = m0 + r;
    const __half* arow = d_xf;
    uint32_t aszA = 0;
    if (gm < cnt) {
        int row = PHASE1 ? d_tok[base + gm] : (base + gm);
        arow = (PHASE1 ? d_xf : d_Hf) + (size_t)row * KTOT;
        aszA = 16;
    }
    const __half* brow = (PHASE1 ? d_w1f : d_w2f) + ((size_t)e * NT + n0 + r) * KTOT;

    uint32_t dstc[4];
#pragma unroll
    for (int j = 0; j < 4; j++) dstc[j] = swz(r, half * 64 + j * 16);

    // ---- compute layout ----
    const int wm  = (wid & 1) * 64;
    const int wn  = (wid >> 1) * 32;
    const int lr  = lid >> 2;

    const int mi    = lid >> 3;
    const int rowAl = wm + (mi & 1) * 8 + (lid & 7);
    const int cbA   = (mi >> 1) * 16;
    const int rowBl = wn + (mi >> 1) * 8 + (lid & 7);
    const int cbB   = (mi & 1) * 16;

    float acc[4][4][4];
#pragma unroll
    for (int i = 0; i < 4; i++)
#pragma unroll
        for (int j = 0; j < 4; j++)
#pragma unroll
            for (int q = 0; q < 4; q++) acc[i][j][q] = 0.f;

    auto issue = [&](int it, int buf) {
        const uint32_t sa = su + (uint32_t)buf * STAGE_BYTES + OFF_A;
        const uint32_t sb = su + (uint32_t)buf * STAGE_BYTES + OFF_B;
        const __half* pa = arow + it * KC + half * 32;
        const __half* pb = brow + it * KC + half * 32;
#pragma unroll
        for (int j = 0; j < 4; j++) {
            cpa16(sa + dstc[j], pa + j * 8, aszA);
            cpa16(sb + dstc[j], pb + j * 8, 16);
        }
    };

    uint32_t Afr[2][16], Bfr[2][8];

    auto ldfrag = [&](uint32_t sa, uint32_t sbb, int kb2, uint32_t* A, uint32_t* B) {
#pragma unroll
        for (int mf = 0; mf < 4; ++mf)
            ldsm4(A + mf * 4, sa + swz(rowAl + mf * 16, kb2 + cbA));
#pragma unroll
        for (int p = 0; p < 2; ++p)
            ldsm4(B + p * 4, sbb + swz(rowBl + p * 16, kb2 + cbB));
    };

    issue(0, 0); CP_COMMIT();
    issue(1, 1); CP_COMMIT();
    CP_WAIT1();
    __syncthreads();
    ldfrag(su + OFF_A, su + OFF_B, 0, Afr[0], Bfr[0]);

    for (int it = 0; it < NK; ++it) {
        const int buf = it % NSTAGE;
        const uint32_t sa  = su + (uint32_t)buf * STAGE_BYTES + OFF_A;
        const uint32_t sbb = su + (uint32_t)buf * STAGE_BYTES + OFF_B;
#pragma unroll
        for (int kk = 0; kk < 4; ++kk) {
            const int cur = kk & 1;
            if (kk < 3) {
                ldfrag(sa, sbb, (kk + 1) * 32, Afr[cur ^ 1], Bfr[cur ^ 1]);
            } else if (it + 1 < NK) {
                if (it + 2 < NK) {
                    issue(it + 2, (it + 2) % NSTAGE);
                    CP_COMMIT();
                    CP_WAIT1();
                } else {
                    CP_WAIT0();
                }
                __syncthreads();
                const int nbuf = (it + 1) % NSTAGE;
                ldfrag(su + (uint32_t)nbuf * STAGE_BYTES + OFF_A,
                       su + (uint32_t)nbuf * STAGE_BYTES + OFF_B,
                       0, Afr[cur ^ 1], Bfr[cur ^ 1]);
            }
#pragma unroll
            for (int mf = 0; mf < 4; ++mf)
#pragma unroll
                for (int nf = 0; nf < 4; ++nf)
                    mma16816(acc[mf][nf], Afr[cur] + mf * 4, Bfr[cur] + nf * 2);
        }
    }

    // ---- epilogue ----
#pragma unroll
    for (int mf = 0; mf < 4; ++mf) {
        const int mrow = m0 + wm + mf * 16 + lr;
#pragma unroll
        for (int hh = 0; hh < 2; ++hh) {
            const int m = mrow + hh * 8;
            if (m < cnt) {
                if (PHASE1) {
                    const size_t hb = (size_t)(base + m) * DFF;
#pragma unroll
                    for (int nf = 0; nf < 4; ++nf) {
                        const int c = n0 + wn + nf * 8 + (lid & 3) * 2;
                        const float2 bv = *(const float2*)(bias + (size_t)e * NT + c);
                        float v0 = acc[mf][nf][hh * 2 + 0] + bv.x;
                        float v1 = acc[mf][nf][hh * 2 + 1] + bv.y;
                        v0 = 0.5f * v0 * (1.0f + erff(v0 * 0.7071067811865475f));
                        v1 = 0.5f * v1 * (1.0f + erff(v1 * 0.7071067811865475f));
                        *(uint32_t*)(d_Hf + hb + c) = pack_h2(v0, v1);
                    }
                } else {
                    const float g = d_gate[base + m];
                    const size_t yb = (size_t)(base + m) * DMODEL;
#pragma unroll
                    for (int nf = 0; nf < 4; ++nf) {
                        const int c = n0 + wn + nf * 8 + (lid & 3) * 2;
                        const float2 bv = *(const float2*)(bias + (size_t)e * NT + c);
                        float2 o;
                        o.x = g * (acc[mf][nf][hh * 2 + 0] + bv.x);
                        o.y = g * (acc[mf][nf][hh * 2 + 1] + bv.y);
                        *(float2*)(d_Y + yb + c) = o;
                    }
                }
            }
        }
    }
}

// ---------------- combine ----------------
__global__ void combine_kernel(float* __restrict__ out) {
    int t  = blockIdx.x;
    int d4 = threadIdx.x;
    int s0 = d_slot_tk[2 * t];
    int s1 = d_slot_tk[2 * t + 1];
    float4 a = *(const float4*)(d_Y + (size_t)s0 * DMODEL + d4 * 4);
    float4 b = *(const float4*)(d_Y + (size_t)s1 * DMODEL + d4 * 4);
    float4 o;
    o.x = a.x + b.x; o.y = a.y + b.y; o.z = a.z + b.z; o.w = a.w + b.w;
    *(float4*)(out + (size_t)t * DMODEL + d4 * 4) = o;
}

// ---------------- launch ----------------
extern "C" void kernel_launch(void* const* d_in, const int* in_sizes, int n_in,
                              void* d_out, int out_size)
{
    const float* x  = (const float*)d_in[0];
    const float* rw = (const float*)d_in[1];
    const float* rb = (const float*)d_in[2];
    const float* w1 = (const float*)d_in[3];
    const float* b1 = (const float*)d_in[4];
    const float* w2 = (const float*)d_in[5];
    const float* b2 = (const float*)d_in[6];
    float* out = (float*)d_out;

    static cudaStream_t s2 = nullptr, s3 = nullptr;
    static cudaEvent_t evF = nullptr, evJ = nullptr, evR = nullptr;
    if (!s2) {
        cudaStreamCreateWithFlags(&s2, cudaStreamNonBlocking);
        cudaStreamCreateWithFlags(&s3, cudaStreamNonBlocking);
        cudaEventCreateWithFlags(&evF, cudaEventDisableTiming);
        cudaEventCreateWithFlags(&evJ, cudaEventDisableTiming);
        cudaEventCreateWithFlags(&evR, cudaEventDisableTiming);
        cudaFuncSetAttribute(gemm_mma<DMODEL, true>,  cudaFuncAttributeMaxDynamicSharedMemorySize, SMEM_BYTES);
        cudaFuncSetAttribute(gemm_mma<DFF,    false>, cudaFuncAttributeMaxDynamicSharedMemorySize, SMEM_BYTES);
    }

    // fork
    cudaEventRecord(evF, 0);
    cudaStreamWaitEvent(s2, evF, 0);
    cudaStreamWaitEvent(s3, evF, 0);

    // s2: w2 conversion (overlaps everything up to GEMM2)
    wcvt2_kernel<<<1184, 256, 0, s2>>>(w2);
    cudaEventRecord(evJ, s2);

    // s3: routing chain
    router_kernel<<<T_TOK / 4, 128, 0, s3>>>(x, rw, rb);
    prefix_scatter_kernel<<<1, 1024, 0, s3>>>();
    cudaEventRecord(evR, s3);

    // default stream: w1 conversion, then GEMMs
    wcvt1_kernel<<<1184, 256>>>(w1);
    cudaStreamWaitEvent(0, evR, 0);
    gemm_mma<DMODEL, true><<<dim3(DFF / BN, MAXMT), 256, SMEM_BYTES>>>(b1);
    cudaStreamWaitEvent(0, evJ, 0);
    gemm_mma<DFF, false><<<dim3(DMODEL / BN, MAXMT), 256, SMEM_BYTES>>>(b2);
    combine_kernel<<<T_TOK, 128>>>(out);
}